// round 3
// baseline (speedup 1.0000x reference)
#include <cuda_runtime.h>
#include <math.h>

#define NB 1024
#define NC 150
#define NH 14
#define NS 196      // 14*14
#define ND 32
#define TOT 29400   // 150*196
#define KGLB 2352   // ceil(0.08*29400)
#define NHEAD 4
#define HD 8

__device__ float g_A[(size_t)NB * NS * NC];        // [b][s][c]
__device__ float g_thr[NB];
__device__ float g_gmax[NB];
__device__ float g_seq[(size_t)NB * NS * ND];      // [b][s][d]
__device__ float g_q[(size_t)NB * NHEAD * NS * HD];
__device__ float g_k[(size_t)NB * NHEAD * NS * HD];
__device__ float g_v[(size_t)NB * NHEAD * NS * HD];
__device__ float g_ctx[(size_t)NB * NS * ND];

// ---------------------------------------------------------------------------
// Kernel 1: conv 9x9 stride2 pad4 + ReLU.  One block per (b, oh).
// smem holds 9 input rows, zero-padded by 4 on each side -> branch-free inner.
// Thread c computes channel c for all 14 ow.
// ---------------------------------------------------------------------------
__global__ void conv_kernel(const float* __restrict__ x,
                            const float* __restrict__ w) {
    __shared__ float row[9][36];  // cols: iw+4, iw in [-4, 31]
    int b = blockIdx.x / NH;
    int oh = blockIdx.x % NH;
    int tid = threadIdx.x;

    for (int i = tid; i < 9 * 36; i += blockDim.x)
        (&row[0][0])[i] = 0.0f;
    __syncthreads();
    for (int i = tid; i < 9 * 28; i += blockDim.x) {
        int kh = i / 28, iw = i % 28;
        int ih = oh * 2 - 4 + kh;
        if (ih >= 0 && ih < 28)
            row[kh][iw + 4] = x[((size_t)b * 28 + ih) * 28 + iw];
    }
    __syncthreads();

    int c = tid;
    if (c < NC) {
        float acc[14];
#pragma unroll
        for (int ow = 0; ow < 14; ++ow) acc[ow] = 0.0f;
        for (int kh = 0; kh < 9; ++kh) {
            float rr[35];
#pragma unroll
            for (int j = 0; j < 35; ++j) rr[j] = row[kh][j];
#pragma unroll
            for (int kw = 0; kw < 9; ++kw) {
                float wv = w[(c * 9 + kh) * 9 + kw];
#pragma unroll
                for (int ow = 0; ow < 14; ++ow)
                    acc[ow] = fmaf(wv, rr[2 * ow + kw], acc[ow]);
            }
        }
        float* out = &g_A[((size_t)b * NS + oh * NH) * NC + c];
#pragma unroll
        for (int ow = 0; ow < 14; ++ow)
            out[(size_t)ow * NC] = fmaxf(acc[ow], 0.0f);
    }
}

// ---------------------------------------------------------------------------
// Kernel 2: per-sample exact KGLB-th largest value (4-level radix select on
// the uint view of nonneg floats) + per-sample global max. One block/sample.
// ---------------------------------------------------------------------------
__global__ void select_kernel() {
    int b = blockIdx.x;
    const float* base = g_A + (size_t)b * TOT;
    __shared__ unsigned hist[256];
    __shared__ unsigned s_prefix;
    __shared__ int s_k;
    __shared__ unsigned s_max;
    int tid = threadIdx.x;
    int nt = blockDim.x;
    if (tid == 0) s_max = 0u;

    unsigned prefix = 0;
    int k = KGLB;
    unsigned mymax = 0;

    for (int level = 0; level < 4; ++level) {
        int shift = 24 - 8 * level;
        for (int i = tid; i < 256; i += nt) hist[i] = 0;
        __syncthreads();
        if (level == 0) {
            for (int i = tid; i < TOT; i += nt) {
                unsigned u = __float_as_uint(base[i]);
                mymax = max(mymax, u);
                atomicAdd(&hist[(u >> 24) & 255], 1u);
            }
        } else {
            int hs = shift + 8;
            for (int i = tid; i < TOT; i += nt) {
                unsigned u = __float_as_uint(base[i]);
                if ((u >> hs) == prefix)
                    atomicAdd(&hist[(u >> shift) & 255], 1u);
            }
        }
        __syncthreads();
        if (tid == 0) {
            int cum = 0;
            unsigned chosen = 0;
            int kk = k;
            for (int bin = 255; bin >= 0; --bin) {
                int c = (int)hist[bin];
                if (cum + c >= k) { chosen = (unsigned)bin; kk = k - cum; break; }
                cum += c;
            }
            s_prefix = (prefix << 8) | chosen;
            s_k = kk;
        }
        __syncthreads();
        prefix = s_prefix;
        k = s_k;
    }

#pragma unroll
    for (int off = 16; off; off >>= 1)
        mymax = max(mymax, __shfl_down_sync(0xffffffffu, mymax, off));
    if ((tid & 31) == 0) atomicMax(&s_max, mymax);
    __syncthreads();
    if (tid == 0) {
        g_thr[b] = __uint_as_float(prefix);
        g_gmax[b] = __uint_as_float(s_max);
    }
}

// ---------------------------------------------------------------------------
// Kernel 3: per-location top-10 channels (value desc, index asc tie-break),
// scatter-weighted channel embedding, /gmax, + 2D sinusoidal PE.
// One warp per location; lane d accumulates output dim d.
// ---------------------------------------------------------------------------
__global__ void topk_embed_kernel(const float* __restrict__ chan_emb) {
    const unsigned FULL = 0xffffffffu;
    int lane = threadIdx.x & 31;
    int gw = blockIdx.x * (blockDim.x >> 5) + (threadIdx.x >> 5);
    if (gw >= NB * NS) return;
    int b = gw / NS;
    int s = gw - b * NS;

    float th = g_thr[b];
    float gm = g_gmax[b];
    float inv = (gm > 0.0f) ? (1.0f / gm) : 0.0f;

    const float* ap = g_A + (size_t)gw * NC;
    float v[5];
#pragma unroll
    for (int i = 0; i < 5; ++i) {
        int c = lane + 32 * i;
        float val = (c < NC) ? ap[c] : 0.0f;
        v[i] = (val >= th) ? val : 0.0f;
    }

    float acc = 0.0f;  // output dim d = lane
    for (int iter = 0; iter < 10; ++iter) {
        float bv = -2.0f;
        int bc = 1 << 20;
#pragma unroll
        for (int i = 0; i < 5; ++i) {
            int c = lane + 32 * i;
            if (v[i] > bv) { bv = v[i]; bc = c; }
        }
#pragma unroll
        for (int off = 16; off; off >>= 1) {
            float ov = __shfl_down_sync(FULL, bv, off);
            int oc = __shfl_down_sync(FULL, bc, off);
            if (ov > bv || (ov == bv && oc < bc)) { bv = ov; bc = oc; }
        }
        bv = __shfl_sync(FULL, bv, 0);
        bc = __shfl_sync(FULL, bc, 0);
        if (bv <= 0.0f) break;  // remaining entries are zeros: contribute 0
        if ((bc & 31) == lane) v[bc >> 5] = -1.0f;  // mark used
        acc = fmaf(bv, chan_emb[bc * ND + lane], acc);
    }
    acc *= inv;

    // 2D sinusoidal PE, dim = lane
    int y = s / NH, xx = s - y * NH;
    int d = lane;
    float pe;
    const float c0 = -(logf(10000.0f) / 16.0f);
    if (d < 16) {
        int j = d >> 1;
        float div = expf(c0 * (float)(2 * j));
        float ang = (float)y * div;
        pe = (d & 1) ? cosf(ang) : sinf(ang);
    } else {
        int dd = d - 16;
        int j = dd >> 1;
        float div = expf(c0 * (float)(2 * j));
        float ang = (float)xx * div;
        pe = (dd & 1) ? cosf(ang) : sinf(ang);
    }
    g_seq[(size_t)gw * ND + lane] = acc + pe;
}

// ---------------------------------------------------------------------------
// Kernel 4a: qkv projection. One warp per (b,s) row; lane computes q/k/v dim
// `lane`. 1/sqrt(HD) folded into q. Writes head-major layout [b][h][s][hd].
// ---------------------------------------------------------------------------
__global__ void qkv_kernel(const float* __restrict__ W,   // [96][32]
                           const float* __restrict__ bias) {
    const unsigned FULL = 0xffffffffu;
    __shared__ float Wt[32][96];  // Wt[j][o] = W[o][j]
    __shared__ float bs[96];
    int tid = threadIdx.x;
    for (int i = tid; i < 96 * 32; i += blockDim.x) {
        int o = i >> 5, j = i & 31;
        Wt[j][o] = W[i];
    }
    for (int i = tid; i < 96; i += blockDim.x) bs[i] = bias[i];
    __syncthreads();

    int lane = tid & 31;
    int r = blockIdx.x * (blockDim.x >> 5) + (tid >> 5);
    if (r >= NB * NS) return;
    int b = r / NS;
    int s = r - b * NS;

    float xv = g_seq[(size_t)r * ND + lane];
    float aq = bs[lane], ak = bs[32 + lane], av = bs[64 + lane];
#pragma unroll
    for (int j = 0; j < 32; ++j) {
        float sv = __shfl_sync(FULL, xv, j);
        aq = fmaf(sv, Wt[j][lane], aq);
        ak = fmaf(sv, Wt[j][32 + lane], ak);
        av = fmaf(sv, Wt[j][64 + lane], av);
    }
    aq *= 0.3535533905932738f;  // 1/sqrt(8)

    int h = lane >> 3, hd = lane & 7;
    size_t o = (((size_t)b * NHEAD + h) * NS + s) * HD + hd;
    g_q[o] = aq;
    g_k[o] = ak;
    g_v[o] = av;
}

// ---------------------------------------------------------------------------
// Kernel 4b: attention per (b,h). K/V staged in smem; thread = query row;
// two-pass exact softmax (pass1 max, pass2 exp+accumulate).
// ---------------------------------------------------------------------------
__global__ void attn_kernel() {
    __shared__ float Ks[NS * HD];
    __shared__ float Vs[NS * HD];
    int b = blockIdx.x >> 2;
    int h = blockIdx.x & 3;
    int tid = threadIdx.x;

    const float* kp = g_k + (((size_t)b * NHEAD + h) * NS) * HD;
    const float* vp = g_v + (((size_t)b * NHEAD + h) * NS) * HD;
    for (int i = tid; i < NS * HD; i += blockDim.x) {
        Ks[i] = kp[i];
        Vs[i] = vp[i];
    }
    __syncthreads();

    if (tid < NS) {
        const float* qp = g_q + ((((size_t)b * NHEAD + h) * NS) + tid) * HD;
        float q[HD];
#pragma unroll
        for (int d = 0; d < HD; ++d) q[d] = qp[d];

        float m = -1e30f;
        for (int t = 0; t < NS; ++t) {
            float dot = 0.0f;
#pragma unroll
            for (int d = 0; d < HD; ++d) dot = fmaf(q[d], Ks[t * HD + d], dot);
            m = fmaxf(m, dot);
        }
        float l = 0.0f;
        float acc[HD];
#pragma unroll
        for (int d = 0; d < HD; ++d) acc[d] = 0.0f;
        for (int t = 0; t < NS; ++t) {
            float dot = 0.0f;
#pragma unroll
            for (int d = 0; d < HD; ++d) dot = fmaf(q[d], Ks[t * HD + d], dot);
            float p = __expf(dot - m);
            l += p;
#pragma unroll
            for (int d = 0; d < HD; ++d) acc[d] = fmaf(p, Vs[t * HD + d], acc[d]);
        }
        float invl = 1.0f / l;
        float* cp = g_ctx + ((size_t)b * NS + tid) * ND + h * HD;
#pragma unroll
        for (int d = 0; d < HD; ++d) cp[d] = acc[d] * invl;
    }
}

// ---------------------------------------------------------------------------
// Kernel 5: out projection. One warp per row; lane computes output dim `lane`.
// ---------------------------------------------------------------------------
__global__ void outproj_kernel(const float* __restrict__ W,   // [32][32]
                               const float* __restrict__ bias,
                               float* __restrict__ out) {
    const unsigned FULL = 0xffffffffu;
    __shared__ float Wt[32][32];  // Wt[j][o] = W[o][j]
    __shared__ float bs[32];
    int tid = threadIdx.x;
    for (int i = tid; i < 32 * 32; i += blockDim.x) {
        int o = i >> 5, j = i & 31;
        Wt[j][o] = W[i];
    }
    if (tid < 32) bs[tid] = bias[tid];
    __syncthreads();

    int lane = tid & 31;
    int r = blockIdx.x * (blockDim.x >> 5) + (tid >> 5);
    if (r >= NB * NS) return;

    float xv = g_ctx[(size_t)r * ND + lane];
    float a = bs[lane];
#pragma unroll
    for (int j = 0; j < 32; ++j) {
        float sv = __shfl_sync(FULL, xv, j);
        a = fmaf(sv, Wt[j][lane], a);
    }
    out[(size_t)r * ND + lane] = a;
}

// ---------------------------------------------------------------------------
extern "C" void kernel_launch(void* const* d_in, const int* in_sizes, int n_in,
                              void* d_out, int out_size) {
    const float* x         = (const float*)d_in[0];  // [1024,1,28,28]
    const float* conv1_w   = (const float*)d_in[1];  // [150,1,9,9]
    const float* chan_emb  = (const float*)d_in[2];  // [150,32]
    const float* in_proj_w = (const float*)d_in[3];  // [96,32]
    const float* in_proj_b = (const float*)d_in[4];  // [96]
    const float* out_proj_w= (const float*)d_in[5];  // [32,32]
    const float* out_proj_b= (const float*)d_in[6];  // [32]
    float* out = (float*)d_out;

    conv_kernel<<<NB * NH, 160>>>(x, conv1_w);
    select_kernel<<<NB, 256>>>();
    topk_embed_kernel<<<(NB * NS) / 8, 256>>>(chan_emb);
    qkv_kernel<<<(NB * NS) / 8, 256>>>(in_proj_w, in_proj_b);
    attn_kernel<<<NB * NHEAD, 256>>>();
    outproj_kernel<<<(NB * NS) / 8, 256>>>(out_proj_w, out_proj_b, out);
}

// round 5
// speedup vs baseline: 1.6883x; 1.6883x over previous
#include <cuda_runtime.h>
#include <math.h>

#define NB 1024
#define NC 150
#define NH 14
#define NS 196      // 14*14
#define ND 32
#define TOT 29400   // 150*196
#define KGLB 2352   // ceil(0.08*29400)
#define NHEAD 4
#define HD 8

typedef unsigned long long u64;

__device__ __forceinline__ u64 pack2(float lo, float hi) {
    u64 r; asm("mov.b64 %0, {%1, %2};" : "=l"(r) : "f"(lo), "f"(hi)); return r;
}
__device__ __forceinline__ void unpack2(u64 v, float& lo, float& hi) {
    asm("mov.b64 {%0, %1}, %2;" : "=f"(lo), "=f"(hi) : "l"(v));
}
__device__ __forceinline__ void ffma2(u64& d, u64 a, u64 b) {
    asm("fma.rn.f32x2 %0, %1, %2, %0;" : "+l"(d) : "l"(a), "l"(b));
}
__device__ __forceinline__ u64 fmul2(u64 a, u64 b) {
    u64 r; asm("mul.rn.f32x2 %0, %1, %2;" : "=l"(r) : "l"(a), "l"(b)); return r;
}

__device__ float g_A[(size_t)NB * NS * NC];        // [b][s][c]
__device__ float g_thr[NB];
__device__ float g_gmax[NB];
__device__ float g_seq[(size_t)NB * NS * ND];      // [b][s][d]
__device__ float g_q[(size_t)NB * NHEAD * NS * HD];
__device__ float g_k[(size_t)NB * NHEAD * NS * HD];
__device__ float g_v[(size_t)NB * NHEAD * NS * HD];
__device__ float g_ctx[(size_t)NB * NS * ND];

// ---------------------------------------------------------------------------
// Kernel 1: conv 9x9 stride2 pad4 + ReLU.  One block per (b, oh).
// ---------------------------------------------------------------------------
__global__ void conv_kernel(const float* __restrict__ x,
                            const float* __restrict__ w) {
    __shared__ float row[9][36];
    int b = blockIdx.x / NH;
    int oh = blockIdx.x % NH;
    int tid = threadIdx.x;

    for (int i = tid; i < 9 * 36; i += blockDim.x)
        (&row[0][0])[i] = 0.0f;
    __syncthreads();
    for (int i = tid; i < 9 * 28; i += blockDim.x) {
        int kh = i / 28, iw = i % 28;
        int ih = oh * 2 - 4 + kh;
        if (ih >= 0 && ih < 28)
            row[kh][iw + 4] = x[((size_t)b * 28 + ih) * 28 + iw];
    }
    __syncthreads();

    int c = tid;
    if (c < NC) {
        float acc[14];
#pragma unroll
        for (int ow = 0; ow < 14; ++ow) acc[ow] = 0.0f;
        for (int kh = 0; kh < 9; ++kh) {
            float rr[35];
#pragma unroll
            for (int j = 0; j < 35; ++j) rr[j] = row[kh][j];
#pragma unroll
            for (int kw = 0; kw < 9; ++kw) {
                float wv = w[(c * 9 + kh) * 9 + kw];
#pragma unroll
                for (int ow = 0; ow < 14; ++ow)
                    acc[ow] = fmaf(wv, rr[2 * ow + kw], acc[ow]);
            }
        }
        float* out = &g_A[((size_t)b * NS + oh * NH) * NC + c];
#pragma unroll
        for (int ow = 0; ow < 14; ++ow)
            out[(size_t)ow * NC] = fmaxf(acc[ow], 0.0f);
    }
}

// ---------------------------------------------------------------------------
// Kernel 2: per-sample exact KGLB-th largest (radix select) + global max.
// float4 scans; zeros skipped (safe: fall-through at every level yields
// prefix 0 -> thr = +0.0, identical downstream semantics).
// ---------------------------------------------------------------------------
__global__ void select_kernel() {
    int b = blockIdx.x;
    const float4* base4 = (const float4*)(g_A + (size_t)b * TOT);
    __shared__ unsigned hist[256];
    __shared__ unsigned s_prefix;
    __shared__ int s_k;
    __shared__ unsigned s_max;
    int tid = threadIdx.x;
    int nt = blockDim.x;
    if (tid == 0) s_max = 0u;

    unsigned prefix = 0;
    int k = KGLB;
    unsigned mymax = 0;

    // ---- level 0 ----
    for (int i = tid; i < 256; i += nt) hist[i] = 0;
    __syncthreads();
    for (int i = tid; i < TOT / 4; i += nt) {
        float4 f = base4[i];
        unsigned u0 = __float_as_uint(f.x);
        unsigned u1 = __float_as_uint(f.y);
        unsigned u2 = __float_as_uint(f.z);
        unsigned u3 = __float_as_uint(f.w);
        mymax = max(mymax, max(max(u0, u1), max(u2, u3)));
        if (u0) atomicAdd(&hist[u0 >> 24], 1u);
        if (u1) atomicAdd(&hist[u1 >> 24], 1u);
        if (u2) atomicAdd(&hist[u2 >> 24], 1u);
        if (u3) atomicAdd(&hist[u3 >> 24], 1u);
    }
    __syncthreads();
    if (tid == 0) {
        int cum = 0; unsigned chosen = 0; int kk = k;
        for (int bin = 255; bin >= 0; --bin) {
            int c = (int)hist[bin];
            if (cum + c >= k) { chosen = (unsigned)bin; kk = k - cum; break; }
            cum += c;
        }
        s_prefix = chosen; s_k = kk;
    }
    __syncthreads();
    prefix = s_prefix; k = s_k;

    // ---- levels 1..3 ----
    for (int level = 1; level < 4; ++level) {
        int shift = 24 - 8 * level;
        int hs = shift + 8;
        for (int i = tid; i < 256; i += nt) hist[i] = 0;
        __syncthreads();
        for (int i = tid; i < TOT / 4; i += nt) {
            float4 f = base4[i];
            unsigned u0 = __float_as_uint(f.x);
            unsigned u1 = __float_as_uint(f.y);
            unsigned u2 = __float_as_uint(f.z);
            unsigned u3 = __float_as_uint(f.w);
            if (u0 && (u0 >> hs) == prefix) atomicAdd(&hist[(u0 >> shift) & 255], 1u);
            if (u1 && (u1 >> hs) == prefix) atomicAdd(&hist[(u1 >> shift) & 255], 1u);
            if (u2 && (u2 >> hs) == prefix) atomicAdd(&hist[(u2 >> shift) & 255], 1u);
            if (u3 && (u3 >> hs) == prefix) atomicAdd(&hist[(u3 >> shift) & 255], 1u);
        }
        __syncthreads();
        if (tid == 0) {
            int cum = 0; unsigned chosen = 0; int kk = k;
            for (int bin = 255; bin >= 0; --bin) {
                int c = (int)hist[bin];
                if (cum + c >= k) { chosen = (unsigned)bin; kk = k - cum; break; }
                cum += c;
            }
            s_prefix = (prefix << 8) | chosen;
            s_k = kk;
        }
        __syncthreads();
        prefix = s_prefix; k = s_k;
    }

#pragma unroll
    for (int off = 16; off; off >>= 1)
        mymax = max(mymax, __shfl_down_sync(0xffffffffu, mymax, off));
    if ((tid & 31) == 0) atomicMax(&s_max, mymax);
    __syncthreads();
    if (tid == 0) {
        g_thr[b] = __uint_as_float(prefix);
        g_gmax[b] = __uint_as_float(s_max);
    }
}

// ---------------------------------------------------------------------------
// Kernel 3: per-location top-10 channels + scatter embed + /gmax + 2D PE.
// One warp per location; lane d accumulates output dim d.
// ---------------------------------------------------------------------------
__global__ void topk_embed_kernel(const float* __restrict__ chan_emb) {
    const unsigned FULL = 0xffffffffu;
    int lane = threadIdx.x & 31;
    int gw = blockIdx.x * (blockDim.x >> 5) + (threadIdx.x >> 5);
    if (gw >= NB * NS) return;
    int b = gw / NS;
    int s = gw - b * NS;

    float th = g_thr[b];
    float gm = g_gmax[b];
    float inv = (gm > 0.0f) ? (1.0f / gm) : 0.0f;

    const float* ap = g_A + (size_t)gw * NC;
    float v[5];
#pragma unroll
    for (int i = 0; i < 5; ++i) {
        int c = lane + 32 * i;
        float val = (c < NC) ? ap[c] : 0.0f;
        v[i] = (val >= th) ? val : 0.0f;
    }

    float acc = 0.0f;
    for (int iter = 0; iter < 10; ++iter) {
        float bv = -2.0f;
        int bc = 1 << 20;
#pragma unroll
        for (int i = 0; i < 5; ++i) {
            int c = lane + 32 * i;
            if (v[i] > bv) { bv = v[i]; bc = c; }
        }
#pragma unroll
        for (int off = 16; off; off >>= 1) {
            float ov = __shfl_down_sync(FULL, bv, off);
            int oc = __shfl_down_sync(FULL, bc, off);
            if (ov > bv || (ov == bv && oc < bc)) { bv = ov; bc = oc; }
        }
        bv = __shfl_sync(FULL, bv, 0);
        bc = __shfl_sync(FULL, bc, 0);
        if (bv <= 0.0f) break;
        if ((bc & 31) == lane) v[bc >> 5] = -1.0f;
        acc = fmaf(bv, chan_emb[bc * ND + lane], acc);
    }
    acc *= inv;

    int y = s / NH, xx = s - y * NH;
    int d = lane;
    float pe;
    const float c0 = -(logf(10000.0f) / 16.0f);
    if (d < 16) {
        int j = d >> 1;
        float div = expf(c0 * (float)(2 * j));
        float ang = (float)y * div;
        pe = (d & 1) ? cosf(ang) : sinf(ang);
    } else {
        int dd = d - 16;
        int j = dd >> 1;
        float div = expf(c0 * (float)(2 * j));
        float ang = (float)xx * div;
        pe = (dd & 1) ? cosf(ang) : sinf(ang);
    }
    g_seq[(size_t)gw * ND + lane] = acc + pe;
}

// ---------------------------------------------------------------------------
// Kernel 4a: qkv projection, register-tiled with packed f32x2 FMA.
// 256 threads/block, 2 rows/thread (r and r+256). Weights pre-packed in smem.
// ---------------------------------------------------------------------------
__global__ void __launch_bounds__(256) qkv_kernel(const float* __restrict__ W,   // [96][32]
                                                  const float* __restrict__ bias) {
    __shared__ u64 Wp[96 * 16];   // Wp[o*16+j] = pack(W[o][2j], W[o][2j+1])
    __shared__ float bs[96];
    int tid = threadIdx.x;
    {
        const float2* w2 = (const float2*)W;
        for (int i = tid; i < 96 * 16; i += 256) {
            float2 f = w2[i];
            Wp[i] = pack2(f.x, f.y);
        }
        if (tid < 96) bs[tid] = bias[tid];
    }
    __syncthreads();

    int r0 = blockIdx.x * 512 + tid;
    int r1 = r0 + 256;

    u64 x0[16], x1[16];
    {
        const float4* p0 = (const float4*)(g_seq + (size_t)r0 * ND);
        const float4* p1 = (const float4*)(g_seq + (size_t)r1 * ND);
#pragma unroll
        for (int i = 0; i < 8; ++i) {
            float4 f = p0[i];
            x0[2 * i] = pack2(f.x, f.y); x0[2 * i + 1] = pack2(f.z, f.w);
            float4 g = p1[i];
            x1[2 * i] = pack2(g.x, g.y); x1[2 * i + 1] = pack2(g.z, g.w);
        }
    }

    int b0 = r0 / NS, s0 = r0 - b0 * NS;
    int b1 = r1 / NS, s1 = r1 - b1 * NS;
    size_t qb0 = (size_t)b0 * (NHEAD * NS * HD) + (size_t)s0 * HD;
    size_t qb1 = (size_t)b1 * (NHEAD * NS * HD) + (size_t)s1 * HD;
    const float SC = 0.3535533905932738f;  // 1/sqrt(8)

#pragma unroll 2
    for (int o = 0; o < 32; ++o) {
        u64 a0 = 0, a1 = 0;
#pragma unroll
        for (int j = 0; j < 16; ++j) {
            u64 w = Wp[o * 16 + j];
            ffma2(a0, x0[j], w);
            ffma2(a1, x1[j], w);
        }
        float l0, h0, l1, h1;
        unpack2(a0, l0, h0); unpack2(a1, l1, h1);
        int off = (o >> 3) * (NS * HD) + (o & 7);
        g_q[qb0 + off] = (l0 + h0 + bs[o]) * SC;
        g_q[qb1 + off] = (l1 + h1 + bs[o]) * SC;
    }
#pragma unroll 2
    for (int o = 32; o < 64; ++o) {
        u64 a0 = 0, a1 = 0;
#pragma unroll
        for (int j = 0; j < 16; ++j) {
            u64 w = Wp[o * 16 + j];
            ffma2(a0, x0[j], w);
            ffma2(a1, x1[j], w);
        }
        float l0, h0, l1, h1;
        unpack2(a0, l0, h0); unpack2(a1, l1, h1);
        int d = o - 32;
        int off = (d >> 3) * (NS * HD) + (d & 7);
        g_k[qb0 + off] = l0 + h0 + bs[o];
        g_k[qb1 + off] = l1 + h1 + bs[o];
    }
#pragma unroll 2
    for (int o = 64; o < 96; ++o) {
        u64 a0 = 0, a1 = 0;
#pragma unroll
        for (int j = 0; j < 16; ++j) {
            u64 w = Wp[o * 16 + j];
            ffma2(a0, x0[j], w);
            ffma2(a1, x1[j], w);
        }
        float l0, h0, l1, h1;
        unpack2(a0, l0, h0); unpack2(a1, l1, h1);
        int d = o - 64;
        int off = (d >> 3) * (NS * HD) + (d & 7);
        g_v[qb0 + off] = l0 + h0 + bs[o];
        g_v[qb1 + off] = l1 + h1 + bs[o];
    }
}

// ---------------------------------------------------------------------------
// Kernel 4b: attention per (b,h). Single-pass EXACT softmax using the
// Cauchy-Schwarz upper bound m' = |q|*max|k| >= all dots (shift-invariant;
// slack << fp32 exp range). K/V in smem as packed f32x2, LDS.128 reads.
// NOTE: the |k|^2 block-max reduction runs with ALL threads participating
// (rows >= NS contribute 0) -- full-mask shuffles must not sit inside a
// divergent guard (R4 deadlock).
// ---------------------------------------------------------------------------
__global__ void __launch_bounds__(224) attn_kernel() {
    __shared__ __align__(16) u64 K2[NS * 4];
    __shared__ __align__(16) u64 V2[NS * 4];
    __shared__ unsigned s_kmax;
    int b = blockIdx.x >> 2;
    int h = blockIdx.x & 3;
    int tid = threadIdx.x;
    if (tid == 0) s_kmax = 0u;

    const float4* kp4 = (const float4*)(g_k + (((size_t)b * NHEAD + h) * NS) * HD);
    const float4* vp4 = (const float4*)(g_v + (((size_t)b * NHEAD + h) * NS) * HD);
    for (int i = tid; i < NS * 2; i += 224) {
        float4 f = kp4[i];
        K2[i * 2] = pack2(f.x, f.y);
        K2[i * 2 + 1] = pack2(f.z, f.w);
        float4 g = vp4[i];
        V2[i * 2] = pack2(g.x, g.y);
        V2[i * 2 + 1] = pack2(g.z, g.w);
    }
    __syncthreads();

    // per-row |k|^2, block max -- ALL 224 threads participate (no divergent
    // guard around the warp shuffles; padding rows contribute 0 >= nothing).
    {
        float kn = 0.0f;
        if (tid < NS) {
            u64 n2 = fmul2(K2[tid * 4], K2[tid * 4]);
            ffma2(n2, K2[tid * 4 + 1], K2[tid * 4 + 1]);
            ffma2(n2, K2[tid * 4 + 2], K2[tid * 4 + 2]);
            ffma2(n2, K2[tid * 4 + 3], K2[tid * 4 + 3]);
            float lo, hi; unpack2(n2, lo, hi);
            kn = lo + hi;
        }
        unsigned u = __float_as_uint(kn);
#pragma unroll
        for (int off = 16; off; off >>= 1)
            u = max(u, __shfl_down_sync(0xffffffffu, u, off));
        if ((tid & 31) == 0) atomicMax(&s_kmax, u);
    }
    __syncthreads();

    if (tid < NS) {
        const float4* qp4 = (const float4*)(g_q + ((((size_t)b * NHEAD + h) * NS) + tid) * HD);
        float4 qa = qp4[0], qb = qp4[1];
        u64 q2[4];
        q2[0] = pack2(qa.x, qa.y); q2[1] = pack2(qa.z, qa.w);
        q2[2] = pack2(qb.x, qb.y); q2[3] = pack2(qb.z, qb.w);
        u64 qn2 = fmul2(q2[0], q2[0]);
        ffma2(qn2, q2[1], q2[1]);
        ffma2(qn2, q2[2], q2[2]);
        ffma2(qn2, q2[3], q2[3]);
        float ql, qh; unpack2(qn2, ql, qh);
        float mprime = sqrtf((ql + qh) * __uint_as_float(s_kmax));

        float l = 0.0f;
        u64 acc0 = 0, acc1 = 0, acc2 = 0, acc3 = 0;
        const ulonglong2* KK = (const ulonglong2*)K2;
        const ulonglong2* VV = (const ulonglong2*)V2;
#pragma unroll 2
        for (int t = 0; t < NS; ++t) {
            ulonglong2 ka = KK[t * 2], kb = KK[t * 2 + 1];
            u64 d2 = fmul2(q2[0], ka.x);
            ffma2(d2, q2[1], ka.y);
            ffma2(d2, q2[2], kb.x);
            ffma2(d2, q2[3], kb.y);
            float dl, dh; unpack2(d2, dl, dh);
            float p = __expf(dl + dh - mprime);
            l += p;
            u64 p2 = pack2(p, p);
            ulonglong2 va = VV[t * 2], vb = VV[t * 2 + 1];
            ffma2(acc0, p2, va.x);
            ffma2(acc1, p2, va.y);
            ffma2(acc2, p2, vb.x);
            ffma2(acc3, p2, vb.y);
        }
        float invl = 1.0f / l;
        float o0, o1, o2, o3, o4, o5, o6, o7;
        unpack2(acc0, o0, o1); unpack2(acc1, o2, o3);
        unpack2(acc2, o4, o5); unpack2(acc3, o6, o7);
        float4* cp = (float4*)(g_ctx + ((size_t)b * NS + tid) * ND + h * HD);
        cp[0] = make_float4(o0 * invl, o1 * invl, o2 * invl, o3 * invl);
        cp[1] = make_float4(o4 * invl, o5 * invl, o6 * invl, o7 * invl);
    }
}

// ---------------------------------------------------------------------------
// Kernel 5: out projection, same register-tiled f32x2 structure as qkv.
// ---------------------------------------------------------------------------
__global__ void __launch_bounds__(256) outproj_kernel(const float* __restrict__ W,   // [32][32]
                                                      const float* __restrict__ bias,
                                                      float* __restrict__ out) {
    __shared__ u64 Wp[32 * 16];
    __shared__ float bs[32];
    int tid = threadIdx.x;
    {
        const float2* w2 = (const float2*)W;
        for (int i = tid; i < 32 * 16; i += 256) {
            float2 f = w2[i];
            Wp[i] = pack2(f.x, f.y);
        }
        if (tid < 32) bs[tid] = bias[tid];
    }
    __syncthreads();

    int r0 = blockIdx.x * 512 + tid;
    int r1 = r0 + 256;

    u64 x0[16], x1[16];
    {
        const float4* p0 = (const float4*)(g_ctx + (size_t)r0 * ND);
        const float4* p1 = (const float4*)(g_ctx + (size_t)r1 * ND);
#pragma unroll
        for (int i = 0; i < 8; ++i) {
            float4 f = p0[i];
            x0[2 * i] = pack2(f.x, f.y); x0[2 * i + 1] = pack2(f.z, f.w);
            float4 g = p1[i];
            x1[2 * i] = pack2(g.x, g.y); x1[2 * i + 1] = pack2(g.z, g.w);
        }
    }

    float* o0 = out + (size_t)r0 * ND;
    float* o1 = out + (size_t)r1 * ND;
#pragma unroll 4
    for (int o = 0; o < 32; ++o) {
        u64 a0 = 0, a1 = 0;
#pragma unroll
        for (int j = 0; j < 16; ++j) {
            u64 w = Wp[o * 16 + j];
            ffma2(a0, x0[j], w);
            ffma2(a1, x1[j], w);
        }
        float l0, h0, l1, h1;
        unpack2(a0, l0, h0); unpack2(a1, l1, h1);
        o0[o] = l0 + h0 + bs[o];
        o1[o] = l1 + h1 + bs[o];
    }
}

// ---------------------------------------------------------------------------
extern "C" void kernel_launch(void* const* d_in, const int* in_sizes, int n_in,
                              void* d_out, int out_size) {
    const float* x          = (const float*)d_in[0];  // [1024,1,28,28]
    const float* conv1_w    = (const float*)d_in[1];  // [150,1,9,9]
    const float* chan_emb   = (const float*)d_in[2];  // [150,32]
    const float* in_proj_w  = (const float*)d_in[3];  // [96,32]
    const float* in_proj_b  = (const float*)d_in[4];  // [96]
    const float* out_proj_w = (const float*)d_in[5];  // [32,32]
    const float* out_proj_b = (const float*)d_in[6];  // [32]
    float* out = (float*)d_out;

    conv_kernel<<<NB * NH, 160>>>(x, conv1_w);
    select_kernel<<<NB, 512>>>();
    topk_embed_kernel<<<(NB * NS) / 8, 256>>>(chan_emb);
    qkv_kernel<<<(NB * NS) / 512, 256>>>(in_proj_w, in_proj_b);
    attn_kernel<<<NB * NHEAD, 224>>>();
    outproj_kernel<<<(NB * NS) / 512, 256>>>(out_proj_w, out_proj_b, out);
}

// round 6
// speedup vs baseline: 1.7438x; 1.0329x over previous
#include <cuda_runtime.h>
#include <math.h>

#define NB 1024
#define NC 150
#define NH 14
#define NS 196      // 14*14
#define ND 32
#define TOT 29400   // 150*196
#define KGLB 2352   // ceil(0.08*29400)
#define NHEAD 4
#define HD 8

typedef unsigned long long u64;

__device__ __forceinline__ u64 pack2(float lo, float hi) {
    u64 r; asm("mov.b64 %0, {%1, %2};" : "=l"(r) : "f"(lo), "f"(hi)); return r;
}
__device__ __forceinline__ void unpack2(u64 v, float& lo, float& hi) {
    asm("mov.b64 {%0, %1}, %2;" : "=f"(lo), "=f"(hi) : "l"(v));
}
__device__ __forceinline__ void ffma2(u64& d, u64 a, u64 b) {
    asm("fma.rn.f32x2 %0, %1, %2, %0;" : "+l"(d) : "l"(a), "l"(b));
}
__device__ __forceinline__ u64 fmul2(u64 a, u64 b) {
    u64 r; asm("mul.rn.f32x2 %0, %1, %2;" : "=l"(r) : "l"(a), "l"(b)); return r;
}

__device__ float g_A[(size_t)NB * NS * NC];        // [b][s][c]
__device__ unsigned g_cand[(size_t)NB * TOT];      // radix-select candidates
__device__ u64 g_wT2[81 * NC];                     // [k][c] = (w,w) splat
__device__ float g_thr[NB];
__device__ float g_gmax[NB];
__device__ float g_seq[(size_t)NB * NS * ND];      // [b][s][d]
__device__ float g_q[(size_t)NB * NHEAD * NS * HD];
__device__ float g_k[(size_t)NB * NHEAD * NS * HD];
__device__ float g_v[(size_t)NB * NHEAD * NS * HD];
__device__ float g_ctx[(size_t)NB * NS * ND];

// ---------------------------------------------------------------------------
// Kernel 0: pre-splat conv weights: g_wT2[k*NC+c] = (w[c][k], w[c][k])
// ---------------------------------------------------------------------------
__global__ void prep_w_kernel(const float* __restrict__ w) {
    int i = blockIdx.x * blockDim.x + threadIdx.x;
    if (i < 81 * NC) {
        int k = i / NC, c = i - k * NC;
        float v = w[c * 81 + k];
        g_wT2[i] = pack2(v, v);
    }
}

// ---------------------------------------------------------------------------
// Kernel 1: conv 9x9 stride2 pad4 + ReLU, f32x2 over ow-pairs.
// Block per (b, oh). row2[kh][j] = (row[j], row[j+2]) gives stride-2 pairs:
// outputs (2p, 2p+1) read inputs (4p+kw, 4p+kw+2) = row2[kh][4p+kw].
// ---------------------------------------------------------------------------
__global__ void __launch_bounds__(160) conv_kernel(const float* __restrict__ x) {
    __shared__ float row[9][36];   // pc = iw+4 in [0,35]
    __shared__ u64 row2[9][33];
    int b = blockIdx.x / NH;
    int oh = blockIdx.x % NH;
    int tid = threadIdx.x;

    for (int i = tid; i < 9 * 36; i += 160)
        (&row[0][0])[i] = 0.0f;
    __syncthreads();
    for (int i = tid; i < 9 * 28; i += 160) {
        int kh = i / 28, iw = i % 28;
        int ih = oh * 2 - 4 + kh;
        if (ih >= 0 && ih < 28)
            row[kh][iw + 4] = x[((size_t)b * 28 + ih) * 28 + iw];
    }
    __syncthreads();
    for (int i = tid; i < 9 * 33; i += 160) {
        int kh = i / 33, j = i - kh * 33;
        row2[kh][j] = pack2(row[kh][j], row[kh][j + 2]);
    }
    __syncthreads();

    int c = tid;
    if (c < NC) {
        u64 acc[7];
#pragma unroll
        for (int p = 0; p < 7; ++p) acc[p] = 0;
        for (int kh = 0; kh < 9; ++kh) {
            u64 rr2[33];
#pragma unroll
            for (int j = 0; j < 33; ++j) rr2[j] = row2[kh][j];
            const u64* wp = &g_wT2[(kh * 9) * NC + c];
#pragma unroll
            for (int kw = 0; kw < 9; ++kw) {
                u64 w2 = wp[kw * NC];
#pragma unroll
                for (int p = 0; p < 7; ++p)
                    ffma2(acc[p], w2, rr2[4 * p + kw]);
            }
        }
        float* out = &g_A[((size_t)b * NS + oh * NH) * NC + c];
#pragma unroll
        for (int p = 0; p < 7; ++p) {
            float lo, hi; unpack2(acc[p], lo, hi);
            out[(size_t)(2 * p) * NC] = fmaxf(lo, 0.0f);
            out[(size_t)(2 * p + 1) * NC] = fmaxf(hi, 0.0f);
        }
    }
}

// ---------------------------------------------------------------------------
// Kernel 2: per-sample exact KGLB-th largest (radix select) + global max.
// Level 0: full float4 scan (zeros skipped -- safe fall-through semantics).
// Level 1: full scan compacts matching candidates + histograms 2nd byte.
// Levels 2-3: scan only the compact candidate list (tiny).
// ---------------------------------------------------------------------------
__global__ void select_kernel() {
    int b = blockIdx.x;
    const float4* base4 = (const float4*)(g_A + (size_t)b * TOT);
    unsigned* cand = g_cand + (size_t)b * TOT;
    __shared__ unsigned hist[256];
    __shared__ unsigned s_prefix;
    __shared__ int s_k;
    __shared__ int s_cnt;
    __shared__ unsigned s_max;
    int tid = threadIdx.x;
    int nt = blockDim.x;
    if (tid == 0) { s_max = 0u; s_cnt = 0; }

    unsigned prefix;
    int k = KGLB;
    unsigned mymax = 0;

    // ---- level 0: full scan, hist of top byte + max ----
    for (int i = tid; i < 256; i += nt) hist[i] = 0;
    __syncthreads();
    for (int i = tid; i < TOT / 4; i += nt) {
        float4 f = base4[i];
        unsigned u0 = __float_as_uint(f.x);
        unsigned u1 = __float_as_uint(f.y);
        unsigned u2 = __float_as_uint(f.z);
        unsigned u3 = __float_as_uint(f.w);
        mymax = max(mymax, max(max(u0, u1), max(u2, u3)));
        if (u0) atomicAdd(&hist[u0 >> 24], 1u);
        if (u1) atomicAdd(&hist[u1 >> 24], 1u);
        if (u2) atomicAdd(&hist[u2 >> 24], 1u);
        if (u3) atomicAdd(&hist[u3 >> 24], 1u);
    }
    __syncthreads();
    if (tid == 0) {
        int cum = 0; unsigned chosen = 0; int kk = k;
        for (int bin = 255; bin >= 0; --bin) {
            int c = (int)hist[bin];
            if (cum + c >= k) { chosen = (unsigned)bin; kk = k - cum; break; }
            cum += c;
        }
        s_prefix = chosen; s_k = kk;
    }
    __syncthreads();
    prefix = s_prefix; k = s_k;

    // ---- level 1: full scan, compact candidates + hist of 2nd byte ----
    for (int i = tid; i < 256; i += nt) hist[i] = 0;
    __syncthreads();
    for (int i = tid; i < TOT / 4; i += nt) {
        float4 f = base4[i];
        unsigned u0 = __float_as_uint(f.x);
        unsigned u1 = __float_as_uint(f.y);
        unsigned u2 = __float_as_uint(f.z);
        unsigned u3 = __float_as_uint(f.w);
        if (u0 && (u0 >> 24) == prefix) { cand[atomicAdd(&s_cnt, 1)] = u0; atomicAdd(&hist[(u0 >> 16) & 255], 1u); }
        if (u1 && (u1 >> 24) == prefix) { cand[atomicAdd(&s_cnt, 1)] = u1; atomicAdd(&hist[(u1 >> 16) & 255], 1u); }
        if (u2 && (u2 >> 24) == prefix) { cand[atomicAdd(&s_cnt, 1)] = u2; atomicAdd(&hist[(u2 >> 16) & 255], 1u); }
        if (u3 && (u3 >> 24) == prefix) { cand[atomicAdd(&s_cnt, 1)] = u3; atomicAdd(&hist[(u3 >> 16) & 255], 1u); }
    }
    __syncthreads();
    int cnt = s_cnt;
    if (tid == 0) {
        int cum = 0; unsigned chosen = 0; int kk = k;
        for (int bin = 255; bin >= 0; --bin) {
            int c = (int)hist[bin];
            if (cum + c >= k) { chosen = (unsigned)bin; kk = k - cum; break; }
            cum += c;
        }
        s_prefix = (prefix << 8) | chosen; s_k = kk;
    }
    __syncthreads();
    prefix = s_prefix; k = s_k;

    // ---- level 2: scan candidates ----
    for (int i = tid; i < 256; i += nt) hist[i] = 0;
    __syncthreads();
    for (int i = tid; i < cnt; i += nt) {
        unsigned u = cand[i];
        if ((u >> 16) == prefix) atomicAdd(&hist[(u >> 8) & 255], 1u);
    }
    __syncthreads();
    if (tid == 0) {
        int cum = 0; unsigned chosen = 0; int kk = k;
        for (int bin = 255; bin >= 0; --bin) {
            int c = (int)hist[bin];
            if (cum + c >= k) { chosen = (unsigned)bin; kk = k - cum; break; }
            cum += c;
        }
        s_prefix = (prefix << 8) | chosen; s_k = kk;
    }
    __syncthreads();
    prefix = s_prefix; k = s_k;

    // ---- level 3: scan candidates ----
    for (int i = tid; i < 256; i += nt) hist[i] = 0;
    __syncthreads();
    for (int i = tid; i < cnt; i += nt) {
        unsigned u = cand[i];
        if ((u >> 8) == prefix) atomicAdd(&hist[u & 255], 1u);
    }
    __syncthreads();
    if (tid == 0) {
        int cum = 0; unsigned chosen = 0;
        for (int bin = 255; bin >= 0; --bin) {
            int c = (int)hist[bin];
            if (cum + c >= k) { chosen = (unsigned)bin; break; }
            cum += c;
        }
        s_prefix = (prefix << 8) | chosen;
    }

#pragma unroll
    for (int off = 16; off; off >>= 1)
        mymax = max(mymax, __shfl_down_sync(0xffffffffu, mymax, off));
    if ((tid & 31) == 0) atomicMax(&s_max, mymax);
    __syncthreads();
    if (tid == 0) {
        g_thr[b] = __uint_as_float(s_prefix);
        g_gmax[b] = __uint_as_float(s_max);
    }
}

// ---------------------------------------------------------------------------
// Kernel 3: per-location top-10 channels + scatter embed + /gmax + 2D PE.
// One warp per location; xor-bfly reductions (result in all lanes).
// ---------------------------------------------------------------------------
__global__ void topk_embed_kernel(const float* __restrict__ chan_emb) {
    const unsigned FULL = 0xffffffffu;
    int lane = threadIdx.x & 31;
    int gw = blockIdx.x * (blockDim.x >> 5) + (threadIdx.x >> 5);
    if (gw >= NB * NS) return;
    int b = gw / NS;
    int s = gw - b * NS;

    float th = g_thr[b];
    float gm = g_gmax[b];
    float inv = (gm > 0.0f) ? (1.0f / gm) : 0.0f;

    const float* ap = g_A + (size_t)gw * NC;
    float v[5];
#pragma unroll
    for (int i = 0; i < 5; ++i) {
        int c = lane + 32 * i;
        float val = (c < NC) ? ap[c] : 0.0f;
        v[i] = (val >= th) ? val : 0.0f;
    }

    float acc = 0.0f;
    for (int iter = 0; iter < 10; ++iter) {
        float bv = -2.0f;
        int bc = 1 << 20;
#pragma unroll
        for (int i = 0; i < 5; ++i) {
            int c = lane + 32 * i;
            if (v[i] > bv) { bv = v[i]; bc = c; }
        }
#pragma unroll
        for (int off = 16; off; off >>= 1) {
            float ov = __shfl_xor_sync(FULL, bv, off);
            int oc = __shfl_xor_sync(FULL, bc, off);
            if (ov > bv || (ov == bv && oc < bc)) { bv = ov; bc = oc; }
        }
        if (bv <= 0.0f) break;
        if ((bc & 31) == lane) v[bc >> 5] = -1.0f;
        acc = fmaf(bv, chan_emb[bc * ND + lane], acc);
    }
    acc *= inv;

    int y = s / NH, xx = s - y * NH;
    int d = lane;
    float pe;
    const float c0 = -(logf(10000.0f) / 16.0f);
    if (d < 16) {
        int j = d >> 1;
        float div = expf(c0 * (float)(2 * j));
        float ang = (float)y * div;
        pe = (d & 1) ? cosf(ang) : sinf(ang);
    } else {
        int dd = d - 16;
        int j = dd >> 1;
        float div = expf(c0 * (float)(2 * j));
        float ang = (float)xx * div;
        pe = (dd & 1) ? cosf(ang) : sinf(ang);
    }
    g_seq[(size_t)gw * ND + lane] = acc + pe;
}

// ---------------------------------------------------------------------------
// Kernel 4a: qkv projection, f32x2 register-tiled, o-pairs for 4-chain ILP.
// 128 threads/block, 2 rows/thread (r, r+128). grid 784.
// ---------------------------------------------------------------------------
__global__ void __launch_bounds__(128) qkv_kernel(const float* __restrict__ W,   // [96][32]
                                                  const float* __restrict__ bias) {
    __shared__ u64 Wp[96 * 16];   // Wp[o*16+j] = (W[o][2j], W[o][2j+1])
    __shared__ float bs[96];
    int tid = threadIdx.x;
    {
        const float2* w2 = (const float2*)W;
        for (int i = tid; i < 96 * 16; i += 128) {
            float2 f = w2[i];
            Wp[i] = pack2(f.x, f.y);
        }
        if (tid < 96) bs[tid] = bias[tid];
    }
    __syncthreads();

    int r0 = blockIdx.x * 256 + tid;
    int r1 = r0 + 128;

    u64 x0[16], x1[16];
    {
        const float4* p0 = (const float4*)(g_seq + (size_t)r0 * ND);
        const float4* p1 = (const float4*)(g_seq + (size_t)r1 * ND);
#pragma unroll
        for (int i = 0; i < 8; ++i) {
            float4 f = p0[i];
            x0[2 * i] = pack2(f.x, f.y); x0[2 * i + 1] = pack2(f.z, f.w);
            float4 g = p1[i];
            x1[2 * i] = pack2(g.x, g.y); x1[2 * i + 1] = pack2(g.z, g.w);
        }
    }

    int b0 = r0 / NS, s0 = r0 - b0 * NS;
    int b1 = r1 / NS, s1 = r1 - b1 * NS;
    size_t qb0 = (size_t)b0 * (NHEAD * NS * HD) + (size_t)s0 * HD;
    size_t qb1 = (size_t)b1 * (NHEAD * NS * HD) + (size_t)s1 * HD;
    const float SC = 0.3535533905932738f;  // 1/sqrt(8)

#pragma unroll 2
    for (int o = 0; o < 32; o += 2) {
        u64 a00 = 0, a10 = 0, a01 = 0, a11 = 0;
#pragma unroll
        for (int j = 0; j < 16; ++j) {
            u64 w0 = Wp[o * 16 + j], w1 = Wp[(o + 1) * 16 + j];
            ffma2(a00, x0[j], w0); ffma2(a10, x1[j], w0);
            ffma2(a01, x0[j], w1); ffma2(a11, x1[j], w1);
        }
        float l, h;
        int offA = (o >> 3) * (NS * HD) + (o & 7);
        int offB = ((o + 1) >> 3) * (NS * HD) + ((o + 1) & 7);
        unpack2(a00, l, h); g_q[qb0 + offA] = (l + h + bs[o]) * SC;
        unpack2(a10, l, h); g_q[qb1 + offA] = (l + h + bs[o]) * SC;
        unpack2(a01, l, h); g_q[qb0 + offB] = (l + h + bs[o + 1]) * SC;
        unpack2(a11, l, h); g_q[qb1 + offB] = (l + h + bs[o + 1]) * SC;
    }
#pragma unroll 2
    for (int o = 32; o < 64; o += 2) {
        u64 a00 = 0, a10 = 0, a01 = 0, a11 = 0;
#pragma unroll
        for (int j = 0; j < 16; ++j) {
            u64 w0 = Wp[o * 16 + j], w1 = Wp[(o + 1) * 16 + j];
            ffma2(a00, x0[j], w0); ffma2(a10, x1[j], w0);
            ffma2(a01, x0[j], w1); ffma2(a11, x1[j], w1);
        }
        float l, h;
        int dA = o - 32, dB = o - 31;
        int offA = (dA >> 3) * (NS * HD) + (dA & 7);
        int offB = (dB >> 3) * (NS * HD) + (dB & 7);
        unpack2(a00, l, h); g_k[qb0 + offA] = l + h + bs[o];
        unpack2(a10, l, h); g_k[qb1 + offA] = l + h + bs[o];
        unpack2(a01, l, h); g_k[qb0 + offB] = l + h + bs[o + 1];
        unpack2(a11, l, h); g_k[qb1 + offB] = l + h + bs[o + 1];
    }
#pragma unroll 2
    for (int o = 64; o < 96; o += 2) {
        u64 a00 = 0, a10 = 0, a01 = 0, a11 = 0;
#pragma unroll
        for (int j = 0; j < 16; ++j) {
            u64 w0 = Wp[o * 16 + j], w1 = Wp[(o + 1) * 16 + j];
            ffma2(a00, x0[j], w0); ffma2(a10, x1[j], w0);
            ffma2(a01, x0[j], w1); ffma2(a11, x1[j], w1);
        }
        float l, h;
        int dA = o - 64, dB = o - 63;
        int offA = (dA >> 3) * (NS * HD) + (dA & 7);
        int offB = (dB >> 3) * (NS * HD) + (dB & 7);
        unpack2(a00, l, h); g_v[qb0 + offA] = l + h + bs[o];
        unpack2(a10, l, h); g_v[qb1 + offA] = l + h + bs[o];
        unpack2(a01, l, h); g_v[qb0 + offB] = l + h + bs[o + 1];
        unpack2(a11, l, h); g_v[qb1 + offB] = l + h + bs[o + 1];
    }
}

// ---------------------------------------------------------------------------
// Kernel 4b: attention. Block = (b, head-pair): 2 heads, 224 threads.
// Thread layout: ha = tid/112, i = tid%112, active i<98, 2 queries/thread
// (2i, 2i+1) -> K/V smem loads amortized over 2 queries. Single-pass EXACT
// softmax via Cauchy-Schwarz bound m' = |q| * max|k|. kmax via smem atomics
// (no divergent warp collectives).
// ---------------------------------------------------------------------------
__global__ void __launch_bounds__(224) attn_kernel() {
    __shared__ __align__(16) u64 K2[2 * NS * 4];
    __shared__ __align__(16) u64 V2[2 * NS * 4];
    __shared__ unsigned s_kmax[2];
    int b = blockIdx.x >> 1;
    int hp = blockIdx.x & 1;      // head pair: heads hp*2, hp*2+1
    int tid = threadIdx.x;
    if (tid < 2) s_kmax[tid] = 0u;

    // 2 heads are contiguous in g_k/g_v: 784 float4 each
    const float4* kp4 = (const float4*)(g_k + (((size_t)b * NHEAD + hp * 2) * NS) * HD);
    const float4* vp4 = (const float4*)(g_v + (((size_t)b * NHEAD + hp * 2) * NS) * HD);
    for (int i = tid; i < 2 * NS * 2; i += 224) {
        float4 f = kp4[i];
        K2[i * 2] = pack2(f.x, f.y);
        K2[i * 2 + 1] = pack2(f.z, f.w);
        float4 g = vp4[i];
        V2[i * 2] = pack2(g.x, g.y);
        V2[i * 2 + 1] = pack2(g.z, g.w);
    }
    __syncthreads();

    // per-row |k|^2 -> per-head max via smem atomicMax
    for (int r = tid; r < 2 * NS; r += 224) {
        u64 n2 = fmul2(K2[r * 4], K2[r * 4]);
        ffma2(n2, K2[r * 4 + 1], K2[r * 4 + 1]);
        ffma2(n2, K2[r * 4 + 2], K2[r * 4 + 2]);
        ffma2(n2, K2[r * 4 + 3], K2[r * 4 + 3]);
        float lo, hi; unpack2(n2, lo, hi);
        atomicMax(&s_kmax[r >= NS ? 1 : 0], __float_as_uint(lo + hi));
    }
    __syncthreads();

    int ha = tid / 112;           // which head within the pair
    int i = tid - ha * 112;
    if (i < 98) {
        int head = hp * 2 + ha;
        int q0 = 2 * i, q1 = 2 * i + 1;
        size_t qrow = (((size_t)b * NHEAD + head) * NS);
        const float4* qp0 = (const float4*)(g_q + (qrow + q0) * HD);
        const float4* qp1 = (const float4*)(g_q + (qrow + q1) * HD);
        float4 qa = qp0[0], qb = qp0[1], qc = qp1[0], qd = qp1[1];
        u64 Q0[4], Q1[4];
        Q0[0] = pack2(qa.x, qa.y); Q0[1] = pack2(qa.z, qa.w);
        Q0[2] = pack2(qb.x, qb.y); Q0[3] = pack2(qb.z, qb.w);
        Q1[0] = pack2(qc.x, qc.y); Q1[1] = pack2(qc.z, qc.w);
        Q1[2] = pack2(qd.x, qd.y); Q1[3] = pack2(qd.z, qd.w);

        float km = __uint_as_float(s_kmax[ha]);
        u64 n0 = fmul2(Q0[0], Q0[0]);
        ffma2(n0, Q0[1], Q0[1]); ffma2(n0, Q0[2], Q0[2]); ffma2(n0, Q0[3], Q0[3]);
        u64 n1 = fmul2(Q1[0], Q1[0]);
        ffma2(n1, Q1[1], Q1[1]); ffma2(n1, Q1[2], Q1[2]); ffma2(n1, Q1[3], Q1[3]);
        float a0, a1, b0f, b1f;
        unpack2(n0, a0, a1); unpack2(n1, b0f, b1f);
        float m0 = sqrtf((a0 + a1) * km);
        float m1 = sqrtf((b0f + b1f) * km);

        float l0 = 0.0f, l1 = 0.0f;
        u64 A0 = 0, A1 = 0, A2 = 0, A3 = 0;   // acc for q0
        u64 B0 = 0, B1 = 0, B2 = 0, B3 = 0;   // acc for q1
        const ulonglong2* KK = (const ulonglong2*)(K2 + ha * NS * 4);
        const ulonglong2* VV = (const ulonglong2*)(V2 + ha * NS * 4);
#pragma unroll 2
        for (int t = 0; t < NS; ++t) {
            ulonglong2 ka = KK[t * 2], kb = KK[t * 2 + 1];
            u64 d0 = fmul2(Q0[0], ka.x);
            ffma2(d0, Q0[1], ka.y); ffma2(d0, Q0[2], kb.x); ffma2(d0, Q0[3], kb.y);
            u64 d1 = fmul2(Q1[0], ka.x);
            ffma2(d1, Q1[1], ka.y); ffma2(d1, Q1[2], kb.x); ffma2(d1, Q1[3], kb.y);
            float e0, f0, e1, f1;
            unpack2(d0, e0, f0); unpack2(d1, e1, f1);
            float p0 = __expf(e0 + f0 - m0);
            float p1 = __expf(e1 + f1 - m1);
            l0 += p0; l1 += p1;
            u64 p02 = pack2(p0, p0), p12 = pack2(p1, p1);
            ulonglong2 va = VV[t * 2], vb = VV[t * 2 + 1];
            ffma2(A0, p02, va.x); ffma2(A1, p02, va.y);
            ffma2(A2, p02, vb.x); ffma2(A3, p02, vb.y);
            ffma2(B0, p12, va.x); ffma2(B1, p12, va.y);
            ffma2(B2, p12, vb.x); ffma2(B3, p12, vb.y);
        }
        float inv0 = 1.0f / l0, inv1 = 1.0f / l1;
        float o0, o1, o2, o3, o4, o5, o6, o7;
        unpack2(A0, o0, o1); unpack2(A1, o2, o3);
        unpack2(A2, o4, o5); unpack2(A3, o6, o7);
        float4* cp0 = (float4*)(g_ctx + ((size_t)b * NS + q0) * ND + head * HD);
        cp0[0] = make_float4(o0 * inv0, o1 * inv0, o2 * inv0, o3 * inv0);
        cp0[1] = make_float4(o4 * inv0, o5 * inv0, o6 * inv0, o7 * inv0);
        unpack2(B0, o0, o1); unpack2(B1, o2, o3);
        unpack2(B2, o4, o5); unpack2(B3, o6, o7);
        float4* cp1 = (float4*)(g_ctx + ((size_t)b * NS + q1) * ND + head * HD);
        cp1[0] = make_float4(o0 * inv1, o1 * inv1, o2 * inv1, o3 * inv1);
        cp1[1] = make_float4(o4 * inv1, o5 * inv1, o6 * inv1, o7 * inv1);
    }
}

// ---------------------------------------------------------------------------
// Kernel 5: out projection, f32x2 register-tiled, o-pairs. 128 thr, 2 rows.
// ---------------------------------------------------------------------------
__global__ void __launch_bounds__(128) outproj_kernel(const float* __restrict__ W,   // [32][32]
                                                      const float* __restrict__ bias,
                                                      float* __restrict__ out) {
    __shared__ u64 Wp[32 * 16];
    __shared__ float bs[32];
    int tid = threadIdx.x;
    {
        const float2* w2 = (const float2*)W;
        for (int i = tid; i < 32 * 16; i += 128) {
            float2 f = w2[i];
            Wp[i] = pack2(f.x, f.y);
        }
        if (tid < 32) bs[tid] = bias[tid];
    }
    __syncthreads();

    int r0 = blockIdx.x * 256 + tid;
    int r1 = r0 + 128;

    u64 x0[16], x1[16];
    {
        const float4* p0 = (const float4*)(g_ctx + (size_t)r0 * ND);
        const float4* p1 = (const float4*)(g_ctx + (size_t)r1 * ND);
#pragma unroll
        for (int i = 0; i < 8; ++i) {
            float4 f = p0[i];
            x0[2 * i] = pack2(f.x, f.y); x0[2 * i + 1] = pack2(f.z, f.w);
            float4 g = p1[i];
            x1[2 * i] = pack2(g.x, g.y); x1[2 * i + 1] = pack2(g.z, g.w);
        }
    }

    float* o0p = out + (size_t)r0 * ND;
    float* o1p = out + (size_t)r1 * ND;
#pragma unroll 2
    for (int o = 0; o < 32; o += 2) {
        u64 a00 = 0, a10 = 0, a01 = 0, a11 = 0;
#pragma unroll
        for (int j = 0; j < 16; ++j) {
            u64 w0 = Wp[o * 16 + j], w1 = Wp[(o + 1) * 16 + j];
            ffma2(a00, x0[j], w0); ffma2(a10, x1[j], w0);
            ffma2(a01, x0[j], w1); ffma2(a11, x1[j], w1);
        }
        float l, h;
        unpack2(a00, l, h); o0p[o] = l + h + bs[o];
        unpack2(a10, l, h); o1p[o] = l + h + bs[o];
        unpack2(a01, l, h); o0p[o + 1] = l + h + bs[o + 1];
        unpack2(a11, l, h); o1p[o + 1] = l + h + bs[o + 1];
    }
}

// ---------------------------------------------------------------------------
extern "C" void kernel_launch(void* const* d_in, const int* in_sizes, int n_in,
                              void* d_out, int out_size) {
    const float* x          = (const float*)d_in[0];  // [1024,1,28,28]
    const float* conv1_w    = (const float*)d_in[1];  // [150,1,9,9]
    const float* chan_emb   = (const float*)d_in[2];  // [150,32]
    const float* in_proj_w  = (const float*)d_in[3];  // [96,32]
    const float* in_proj_b  = (const float*)d_in[4];  // [96]
    const float* out_proj_w = (const float*)d_in[5];  // [32,32]
    const float* out_proj_b = (const float*)d_in[6];  // [32]
    float* out = (float*)d_out;

    prep_w_kernel<<<(81 * NC + 255) / 256, 256>>>(conv1_w);
    conv_kernel<<<NB * NH, 160>>>(x);
    select_kernel<<<NB, 512>>>();
    topk_embed_kernel<<<(NB * NS) / 8, 256>>>(chan_emb);
    qkv_kernel<<<(NB * NS) / 256, 128>>>(in_proj_w, in_proj_b);
    attn_kernel<<<NB * 2, 224>>>();
    outproj_kernel<<<(NB * NS) / 256, 128>>>(out_proj_w, out_proj_b, out);
}

// round 8
// speedup vs baseline: 2.1322x; 1.2227x over previous
#include <cuda_runtime.h>
#include <math.h>

#define NB 1024
#define NC 150
#define NCP 152     // padded channel stride (float4-aligned); pad stays 0
#define NH 14
#define NS 196      // 14*14
#define ND 32
#define TOTP (NS * NCP)   // padded per-sample extent = 29792
#define KGLB 2352   // ceil(0.08 * 150*196)
#define NHEAD 4
#define HD 8

typedef unsigned long long u64;

__device__ __forceinline__ u64 pack2(float lo, float hi) {
    u64 r; asm("mov.b64 %0, {%1, %2};" : "=l"(r) : "f"(lo), "f"(hi)); return r;
}
__device__ __forceinline__ void unpack2(u64 v, float& lo, float& hi) {
    asm("mov.b64 {%0, %1}, %2;" : "=f"(lo), "=f"(hi) : "l"(v));
}
__device__ __forceinline__ void ffma2(u64& d, u64 a, u64 b) {
    asm("fma.rn.f32x2 %0, %1, %2, %0;" : "+l"(d) : "l"(a), "l"(b));
}
__device__ __forceinline__ u64 fmul2(u64 a, u64 b) {
    u64 r; asm("mul.rn.f32x2 %0, %1, %2;" : "=l"(r) : "l"(a), "l"(b)); return r;
}

__device__ float g_A[(size_t)NB * NS * NCP];       // [b][s][c], c-pad zeroed
__device__ unsigned g_cand[(size_t)NB * TOTP];     // radix-select candidates
__device__ u64 g_wT2[81 * NC];                     // [k][c] = (w,w) splat
__device__ float g_pe[NS * ND];                    // 2D sinusoidal PE table
__device__ float g_thr[NB];
__device__ float g_gmax[NB];
__device__ float g_q[(size_t)NB * NHEAD * NS * HD];
__device__ float g_k[(size_t)NB * NHEAD * NS * HD];
__device__ float g_v[(size_t)NB * NHEAD * NS * HD];
__device__ float g_ctx[(size_t)NB * NS * ND];

// ---------------------------------------------------------------------------
// Kernel 0a: pre-splat conv weights: g_wT2[k*NC+c] = (w[c][k], w[c][k])
// ---------------------------------------------------------------------------
__global__ void prep_w_kernel(const float* __restrict__ w) {
    int i = blockIdx.x * blockDim.x + threadIdx.x;
    if (i < 81 * NC) {
        int k = i / NC, c = i - k * NC;
        float v = w[c * 81 + k];
        g_wT2[i] = pack2(v, v);
    }
}

// ---------------------------------------------------------------------------
// Kernel 0b: 2D sinusoidal PE table (batch-independent). 196 blocks x 32 thr.
// ---------------------------------------------------------------------------
__global__ void pe_kernel() {
    int s = blockIdx.x;
    int d = threadIdx.x;
    int y = s / NH, xx = s - y * NH;
    const float c0 = -(logf(10000.0f) / 16.0f);
    float pe;
    if (d < 16) {
        int j = d >> 1;
        float div = expf(c0 * (float)(2 * j));
        float ang = (float)y * div;
        pe = (d & 1) ? cosf(ang) : sinf(ang);
    } else {
        int dd = d - 16;
        int j = dd >> 1;
        float div = expf(c0 * (float)(2 * j));
        float ang = (float)xx * div;
        pe = (dd & 1) ? cosf(ang) : sinf(ang);
    }
    g_pe[s * ND + d] = pe;
}

// ---------------------------------------------------------------------------
// Kernel 1: conv 9x9 stride2 pad4 + ReLU, f32x2 over ow-pairs.
// ---------------------------------------------------------------------------
__global__ void __launch_bounds__(160) conv_kernel(const float* __restrict__ x) {
    __shared__ float row[9][36];
    __shared__ u64 row2[9][33];
    int b = blockIdx.x / NH;
    int oh = blockIdx.x % NH;
    int tid = threadIdx.x;

    for (int i = tid; i < 9 * 36; i += 160)
        (&row[0][0])[i] = 0.0f;
    __syncthreads();
    for (int i = tid; i < 9 * 28; i += 160) {
        int kh = i / 28, iw = i % 28;
        int ih = oh * 2 - 4 + kh;
        if (ih >= 0 && ih < 28)
            row[kh][iw + 4] = x[((size_t)b * 28 + ih) * 28 + iw];
    }
    __syncthreads();
    for (int i = tid; i < 9 * 33; i += 160) {
        int kh = i / 33, j = i - kh * 33;
        row2[kh][j] = pack2(row[kh][j], row[kh][j + 2]);
    }
    __syncthreads();

    int c = tid;
    if (c < NC) {
        u64 acc[7];
#pragma unroll
        for (int p = 0; p < 7; ++p) acc[p] = 0;
        for (int kh = 0; kh < 9; ++kh) {
            u64 rr2[33];
#pragma unroll
            for (int j = 0; j < 33; ++j) rr2[j] = row2[kh][j];
            const u64* wp = &g_wT2[(kh * 9) * NC + c];
#pragma unroll
            for (int kw = 0; kw < 9; ++kw) {
                u64 w2 = wp[kw * NC];
#pragma unroll
                for (int p = 0; p < 7; ++p)
                    ffma2(acc[p], w2, rr2[4 * p + kw]);
            }
        }
        float* out = &g_A[((size_t)b * NS + oh * NH) * NCP + c];
#pragma unroll
        for (int p = 0; p < 7; ++p) {
            float lo, hi; unpack2(acc[p], lo, hi);
            out[(size_t)(2 * p) * NCP] = fmaxf(lo, 0.0f);
            out[(size_t)(2 * p + 1) * NCP] = fmaxf(hi, 0.0f);
        }
    }
}

// ---------------------------------------------------------------------------
// Kernel 2: per-sample exact KGLB-th largest (radix select) + global max.
// Zeros (incl. channel padding) are skipped -- safe fall-through semantics.
// ---------------------------------------------------------------------------
__global__ void select_kernel() {
    int b = blockIdx.x;
    const float4* base4 = (const float4*)(g_A + (size_t)b * TOTP);
    unsigned* cand = g_cand + (size_t)b * TOTP;
    __shared__ unsigned hist[256];
    __shared__ unsigned s_prefix;
    __shared__ int s_k;
    __shared__ int s_cnt;
    __shared__ unsigned s_max;
    int tid = threadIdx.x;
    int nt = blockDim.x;
    if (tid == 0) { s_max = 0u; s_cnt = 0; }

    unsigned prefix;
    int k = KGLB;
    unsigned mymax = 0;

    // ---- level 0: full scan, hist of top byte + max ----
    for (int i = tid; i < 256; i += nt) hist[i] = 0;
    __syncthreads();
    for (int i = tid; i < TOTP / 4; i += nt) {
        float4 f = base4[i];
        unsigned u0 = __float_as_uint(f.x);
        unsigned u1 = __float_as_uint(f.y);
        unsigned u2 = __float_as_uint(f.z);
        unsigned u3 = __float_as_uint(f.w);
        mymax = max(mymax, max(max(u0, u1), max(u2, u3)));
        if (u0) atomicAdd(&hist[u0 >> 24], 1u);
        if (u1) atomicAdd(&hist[u1 >> 24], 1u);
        if (u2) atomicAdd(&hist[u2 >> 24], 1u);
        if (u3) atomicAdd(&hist[u3 >> 24], 1u);
    }
    __syncthreads();
    if (tid == 0) {
        int cum = 0; unsigned chosen = 0; int kk = k;
        for (int bin = 255; bin >= 0; --bin) {
            int c = (int)hist[bin];
            if (cum + c >= k) { chosen = (unsigned)bin; kk = k - cum; break; }
            cum += c;
        }
        s_prefix = chosen; s_k = kk;
    }
    __syncthreads();
    prefix = s_prefix; k = s_k;

    // ---- level 1: full scan, compact candidates + hist of 2nd byte ----
    for (int i = tid; i < 256; i += nt) hist[i] = 0;
    __syncthreads();
    for (int i = tid; i < TOTP / 4; i += nt) {
        float4 f = base4[i];
        unsigned u0 = __float_as_uint(f.x);
        unsigned u1 = __float_as_uint(f.y);
        unsigned u2 = __float_as_uint(f.z);
        unsigned u3 = __float_as_uint(f.w);
        if (u0 && (u0 >> 24) == prefix) { cand[atomicAdd(&s_cnt, 1)] = u0; atomicAdd(&hist[(u0 >> 16) & 255], 1u); }
        if (u1 && (u1 >> 24) == prefix) { cand[atomicAdd(&s_cnt, 1)] = u1; atomicAdd(&hist[(u1 >> 16) & 255], 1u); }
        if (u2 && (u2 >> 24) == prefix) { cand[atomicAdd(&s_cnt, 1)] = u2; atomicAdd(&hist[(u2 >> 16) & 255], 1u); }
        if (u3 && (u3 >> 24) == prefix) { cand[atomicAdd(&s_cnt, 1)] = u3; atomicAdd(&hist[(u3 >> 16) & 255], 1u); }
    }
    __syncthreads();
    int cnt = s_cnt;
    if (tid == 0) {
        int cum = 0; unsigned chosen = 0; int kk = k;
        for (int bin = 255; bin >= 0; --bin) {
            int c = (int)hist[bin];
            if (cum + c >= k) { chosen = (unsigned)bin; kk = k - cum; break; }
            cum += c;
        }
        s_prefix = (prefix << 8) | chosen; s_k = kk;
    }
    __syncthreads();
    prefix = s_prefix; k = s_k;

    // ---- level 2: scan candidates ----
    for (int i = tid; i < 256; i += nt) hist[i] = 0;
    __syncthreads();
    for (int i = tid; i < cnt; i += nt) {
        unsigned u = cand[i];
        if ((u >> 16) == prefix) atomicAdd(&hist[(u >> 8) & 255], 1u);
    }
    __syncthreads();
    if (tid == 0) {
        int cum = 0; unsigned chosen = 0; int kk = k;
        for (int bin = 255; bin >= 0; --bin) {
            int c = (int)hist[bin];
            if (cum + c >= k) { chosen = (unsigned)bin; kk = k - cum; break; }
            cum += c;
        }
        s_prefix = (prefix << 8) | chosen; s_k = kk;
    }
    __syncthreads();
    prefix = s_prefix; k = s_k;

    // ---- level 3: scan candidates ----
    for (int i = tid; i < 256; i += nt) hist[i] = 0;
    __syncthreads();
    for (int i = tid; i < cnt; i += nt) {
        unsigned u = cand[i];
        if ((u >> 8) == prefix) atomicAdd(&hist[u & 255], 1u);
    }
    __syncthreads();
    if (tid == 0) {
        int cum = 0; unsigned chosen = 0;
        for (int bin = 255; bin >= 0; --bin) {
            int c = (int)hist[bin];
            if (cum + c >= k) { chosen = (unsigned)bin; break; }
            cum += c;
        }
        s_prefix = (prefix << 8) | chosen;
    }

#pragma unroll
    for (int off = 16; off; off >>= 1)
        mymax = max(mymax, __shfl_down_sync(0xffffffffu, mymax, off));
    if ((tid & 31) == 0) atomicMax(&s_max, mymax);
    __syncthreads();
    if (tid == 0) {
        g_thr[b] = __uint_as_float(s_prefix);
        g_gmax[b] = __uint_as_float(s_max);
    }
}

// ---------------------------------------------------------------------------
// Kernel 3 (FUSED): per-location top-10 + scatter embed + /gmax + PE + qkv.
// One THREAD per location; padded row stride (152) keeps float4 loads aligned.
// Padding zeros can never enter the top-10 (a > tv[9] fails, tv[9] >= 0).
// ---------------------------------------------------------------------------
__global__ void __launch_bounds__(128) topk_qkv_kernel(
        const float* __restrict__ chan_emb,     // [150][32]
        const float* __restrict__ W,            // [96][32]
        const float* __restrict__ bias) {       // [96]
    __shared__ u64 Emb[NC * 16];   // 19.2 KB
    __shared__ u64 Wp[96 * 16];    // 12.3 KB
    __shared__ float bs[96];
    int tid = threadIdx.x;
    {
        const float2* e2 = (const float2*)chan_emb;
        for (int i = tid; i < NC * 16; i += 128) {
            float2 f = e2[i]; Emb[i] = pack2(f.x, f.y);
        }
        const float2* w2 = (const float2*)W;
        for (int i = tid; i < 96 * 16; i += 128) {
            float2 f = w2[i]; Wp[i] = pack2(f.x, f.y);
        }
        if (tid < 96) bs[tid] = bias[tid];
    }
    __syncthreads();

    int loc = blockIdx.x * 128 + tid;          // exact: grid = NB*NS/128
    int b = loc / NS, s = loc - b * NS;
    float th = g_thr[b];
    float gm = g_gmax[b];
    float inv = (gm > 0.0f) ? (1.0f / gm) : 0.0f;

    // ---- top-10 scan (ascending channel order; 38 aligned float4) ----
    float tv[10];
    int tc[10];
#pragma unroll
    for (int j = 0; j < 10; ++j) { tv[j] = 0.0f; tc[j] = 0; }

    const float4* r4 = (const float4*)(g_A + (size_t)loc * NCP);
#pragma unroll 4
    for (int i = 0; i < 38; ++i) {
        float4 f = r4[i];
        float vals[4] = {f.x, f.y, f.z, f.w};
#pragma unroll
        for (int q = 0; q < 4; ++q) {
            float a = vals[q];
            if (a >= th && a > tv[9]) {
                float cv = a; int cc = 4 * i + q;
#pragma unroll
                for (int j = 0; j < 10; ++j) {
                    bool sw = cv > tv[j];
                    float nv = sw ? tv[j] : cv;
                    int nc2 = sw ? tc[j] : cc;
                    tv[j] = sw ? cv : tv[j];
                    tc[j] = sw ? cc : tc[j];
                    cv = nv; cc = nc2;
                }
            }
        }
    }

    // ---- embed accumulate: x[t] += v * emb[c][2t:2t+2] ----
    u64 x[16];
#pragma unroll
    for (int t = 0; t < 16; ++t) x[t] = 0;
#pragma unroll
    for (int j = 0; j < 10; ++j) {
        if (tv[j] > 0.0f) {
            u64 vv = pack2(tv[j], tv[j]);
            const u64* ep = &Emb[tc[j] * 16];
#pragma unroll
            for (int t = 0; t < 16; ++t)
                ffma2(x[t], vv, ep[t]);
        }
    }

    // ---- normalize + PE: x = x*inv + pe ----
    {
        u64 inv2 = pack2(inv, inv);
        const float4* pe4 = (const float4*)(g_pe + s * ND);
#pragma unroll
        for (int t = 0; t < 8; ++t) {
            float4 p = pe4[t];
            u64 y0 = pack2(p.x, p.y);
            u64 y1 = pack2(p.z, p.w);
            ffma2(y0, x[2 * t], inv2);
            ffma2(y1, x[2 * t + 1], inv2);
            x[2 * t] = y0;
            x[2 * t + 1] = y1;
        }
    }

    // ---- qkv projection: 96 outputs, 4 at a time (4 FFMA2 chains) ----
    size_t qb = (size_t)b * (NHEAD * NS * HD) + (size_t)s * HD;
    const float SC = 0.3535533905932738f;  // 1/sqrt(8)

#pragma unroll 2
    for (int o = 0; o < 32; o += 4) {
        u64 a0 = 0, a1 = 0, a2 = 0, a3 = 0;
#pragma unroll
        for (int j = 0; j < 16; ++j) {
            u64 xv = x[j];
            ffma2(a0, xv, Wp[(o + 0) * 16 + j]);
            ffma2(a1, xv, Wp[(o + 1) * 16 + j]);
            ffma2(a2, xv, Wp[(o + 2) * 16 + j]);
            ffma2(a3, xv, Wp[(o + 3) * 16 + j]);
        }
        float l, h, r0, r1, r2, r3;
        unpack2(a0, l, h); r0 = (l + h + bs[o + 0]) * SC;
        unpack2(a1, l, h); r1 = (l + h + bs[o + 1]) * SC;
        unpack2(a2, l, h); r2 = (l + h + bs[o + 2]) * SC;
        unpack2(a3, l, h); r3 = (l + h + bs[o + 3]) * SC;
        *(float4*)(g_q + qb + (o >> 3) * (NS * HD) + (o & 7)) = make_float4(r0, r1, r2, r3);
    }
#pragma unroll 2
    for (int o = 32; o < 64; o += 4) {
        u64 a0 = 0, a1 = 0, a2 = 0, a3 = 0;
#pragma unroll
        for (int j = 0; j < 16; ++j) {
            u64 xv = x[j];
            ffma2(a0, xv, Wp[(o + 0) * 16 + j]);
            ffma2(a1, xv, Wp[(o + 1) * 16 + j]);
            ffma2(a2, xv, Wp[(o + 2) * 16 + j]);
            ffma2(a3, xv, Wp[(o + 3) * 16 + j]);
        }
        float l, h, r0, r1, r2, r3;
        unpack2(a0, l, h); r0 = l + h + bs[o + 0];
        unpack2(a1, l, h); r1 = l + h + bs[o + 1];
        unpack2(a2, l, h); r2 = l + h + bs[o + 2];
        unpack2(a3, l, h); r3 = l + h + bs[o + 3];
        int d = o - 32;
        *(float4*)(g_k + qb + (d >> 3) * (NS * HD) + (d & 7)) = make_float4(r0, r1, r2, r3);
    }
#pragma unroll 2
    for (int o = 64; o < 96; o += 4) {
        u64 a0 = 0, a1 = 0, a2 = 0, a3 = 0;
#pragma unroll
        for (int j = 0; j < 16; ++j) {
            u64 xv = x[j];
            ffma2(a0, xv, Wp[(o + 0) * 16 + j]);
            ffma2(a1, xv, Wp[(o + 1) * 16 + j]);
            ffma2(a2, xv, Wp[(o + 2) * 16 + j]);
            ffma2(a3, xv, Wp[(o + 3) * 16 + j]);
        }
        float l, h, r0, r1, r2, r3;
        unpack2(a0, l, h); r0 = l + h + bs[o + 0];
        unpack2(a1, l, h); r1 = l + h + bs[o + 1];
        unpack2(a2, l, h); r2 = l + h + bs[o + 2];
        unpack2(a3, l, h); r3 = l + h + bs[o + 3];
        int d = o - 64;
        *(float4*)(g_v + qb + (d >> 3) * (NS * HD) + (d & 7)) = make_float4(r0, r1, r2, r3);
    }
}

// ---------------------------------------------------------------------------
// Kernel 4b: attention. Block = (b, head-pair): 2 heads, 224 threads.
// Single-pass EXACT softmax via Cauchy-Schwarz bound m' = |q| * max|k|.
// ---------------------------------------------------------------------------
__global__ void __launch_bounds__(224) attn_kernel() {
    __shared__ __align__(16) u64 K2[2 * NS * 4];
    __shared__ __align__(16) u64 V2[2 * NS * 4];
    __shared__ unsigned s_kmax[2];
    int b = blockIdx.x >> 1;
    int hp = blockIdx.x & 1;
    int tid = threadIdx.x;
    if (tid < 2) s_kmax[tid] = 0u;

    const float4* kp4 = (const float4*)(g_k + (((size_t)b * NHEAD + hp * 2) * NS) * HD);
    const float4* vp4 = (const float4*)(g_v + (((size_t)b * NHEAD + hp * 2) * NS) * HD);
    for (int i = tid; i < 2 * NS * 2; i += 224) {
        float4 f = kp4[i];
        K2[i * 2] = pack2(f.x, f.y);
        K2[i * 2 + 1] = pack2(f.z, f.w);
        float4 g = vp4[i];
        V2[i * 2] = pack2(g.x, g.y);
        V2[i * 2 + 1] = pack2(g.z, g.w);
    }
    __syncthreads();

    for (int r = tid; r < 2 * NS; r += 224) {
        u64 n2 = fmul2(K2[r * 4], K2[r * 4]);
        ffma2(n2, K2[r * 4 + 1], K2[r * 4 + 1]);
        ffma2(n2, K2[r * 4 + 2], K2[r * 4 + 2]);
        ffma2(n2, K2[r * 4 + 3], K2[r * 4 + 3]);
        float lo, hi; unpack2(n2, lo, hi);
        atomicMax(&s_kmax[r >= NS ? 1 : 0], __float_as_uint(lo + hi));
    }
    __syncthreads();

    int ha = tid / 112;
    int i = tid - ha * 112;
    if (i < 98) {
        int head = hp * 2 + ha;
        int q0 = 2 * i, q1 = 2 * i + 1;
        size_t qrow = (((size_t)b * NHEAD + head) * NS);
        const float4* qp0 = (const float4*)(g_q + (qrow + q0) * HD);
        const float4* qp1 = (const float4*)(g_q + (qrow + q1) * HD);
        float4 qa = qp0[0], qb = qp0[1], qc = qp1[0], qd = qp1[1];
        u64 Q0[4], Q1[4];
        Q0[0] = pack2(qa.x, qa.y); Q0[1] = pack2(qa.z, qa.w);
        Q0[2] = pack2(qb.x, qb.y); Q0[3] = pack2(qb.z, qb.w);
        Q1[0] = pack2(qc.x, qc.y); Q1[1] = pack2(qc.z, qc.w);
        Q1[2] = pack2(qd.x, qd.y); Q1[3] = pack2(qd.z, qd.w);

        float km = __uint_as_float(s_kmax[ha]);
        u64 n0 = fmul2(Q0[0], Q0[0]);
        ffma2(n0, Q0[1], Q0[1]); ffma2(n0, Q0[2], Q0[2]); ffma2(n0, Q0[3], Q0[3]);
        u64 n1 = fmul2(Q1[0], Q1[0]);
        ffma2(n1, Q1[1], Q1[1]); ffma2(n1, Q1[2], Q1[2]); ffma2(n1, Q1[3], Q1[3]);
        float a0, a1, b0f, b1f;
        unpack2(n0, a0, a1); unpack2(n1, b0f, b1f);
        float m0 = sqrtf((a0 + a1) * km);
        float m1 = sqrtf((b0f + b1f) * km);

        float l0 = 0.0f, l1 = 0.0f;
        u64 A0 = 0, A1 = 0, A2 = 0, A3 = 0;
        u64 B0 = 0, B1 = 0, B2 = 0, B3 = 0;
        const ulonglong2* KK = (const ulonglong2*)(K2 + ha * NS * 4);
        const ulonglong2* VV = (const ulonglong2*)(V2 + ha * NS * 4);
#pragma unroll 2
        for (int t = 0; t < NS; ++t) {
            ulonglong2 ka = KK[t * 2], kb = KK[t * 2 + 1];
            u64 d0 = fmul2(Q0[0], ka.x);
            ffma2(d0, Q0[1], ka.y); ffma2(d0, Q0[2], kb.x); ffma2(d0, Q0[3], kb.y);
            u64 d1 = fmul2(Q1[0], ka.x);
            ffma2(d1, Q1[1], ka.y); ffma2(d1, Q1[2], kb.x); ffma2(d1, Q1[3], kb.y);
            float e0, f0, e1, f1;
            unpack2(d0, e0, f0); unpack2(d1, e1, f1);
            float p0 = __expf(e0 + f0 - m0);
            float p1 = __expf(e1 + f1 - m1);
            l0 += p0; l1 += p1;
            u64 p02 = pack2(p0, p0), p12 = pack2(p1, p1);
            ulonglong2 va = VV[t * 2], vb = VV[t * 2 + 1];
            ffma2(A0, p02, va.x); ffma2(A1, p02, va.y);
            ffma2(A2, p02, vb.x); ffma2(A3, p02, vb.y);
            ffma2(B0, p12, va.x); ffma2(B1, p12, va.y);
            ffma2(B2, p12, vb.x); ffma2(B3, p12, vb.y);
        }
        float inv0 = 1.0f / l0, inv1 = 1.0f / l1;
        float o0, o1, o2, o3, o4, o5, o6, o7;
        unpack2(A0, o0, o1); unpack2(A1, o2, o3);
        unpack2(A2, o4, o5); unpack2(A3, o6, o7);
        float4* cp0 = (float4*)(g_ctx + ((size_t)b * NS + q0) * ND + head * HD);
        cp0[0] = make_float4(o0 * inv0, o1 * inv0, o2 * inv0, o3 * inv0);
        cp0[1] = make_float4(o4 * inv0, o5 * inv0, o6 * inv0, o7 * inv0);
        unpack2(B0, o0, o1); unpack2(B1, o2, o3);
        unpack2(B2, o4, o5); unpack2(B3, o6, o7);
        float4* cp1 = (float4*)(g_ctx + ((size_t)b * NS + q1) * ND + head * HD);
        cp1[0] = make_float4(o0 * inv1, o1 * inv1, o2 * inv1, o3 * inv1);
        cp1[1] = make_float4(o4 * inv1, o5 * inv1, o6 * inv1, o7 * inv1);
    }
}

// ---------------------------------------------------------------------------
// Kernel 5: out projection, f32x2 register-tiled, o-pairs. 128 thr, 2 rows.
// ---------------------------------------------------------------------------
__global__ void __launch_bounds__(128) outproj_kernel(const float* __restrict__ W,
                                                      const float* __restrict__ bias,
                                                      float* __restrict__ out) {
    __shared__ u64 Wp[32 * 16];
    __shared__ float bs[32];
    int tid = threadIdx.x;
    {
        const float2* w2 = (const float2*)W;
        for (int i = tid; i < 32 * 16; i += 128) {
            float2 f = w2[i];
            Wp[i] = pack2(f.x, f.y);
        }
        if (tid < 32) bs[tid] = bias[tid];
    }
    __syncthreads();

    int r0 = blockIdx.x * 256 + tid;
    int r1 = r0 + 128;

    u64 x0[16], x1[16];
    {
        const float4* p0 = (const float4*)(g_ctx + (size_t)r0 * ND);
        const float4* p1 = (const float4*)(g_ctx + (size_t)r1 * ND);
#pragma unroll
        for (int i = 0; i < 8; ++i) {
            float4 f = p0[i];
            x0[2 * i] = pack2(f.x, f.y); x0[2 * i + 1] = pack2(f.z, f.w);
            float4 g = p1[i];
            x1[2 * i] = pack2(g.x, g.y); x1[2 * i + 1] = pack2(g.z, g.w);
        }
    }

    float* o0p = out + (size_t)r0 * ND;
    float* o1p = out + (size_t)r1 * ND;
#pragma unroll 2
    for (int o = 0; o < 32; o += 2) {
        u64 a00 = 0, a10 = 0, a01 = 0, a11 = 0;
#pragma unroll
        for (int j = 0; j < 16; ++j) {
            u64 w0 = Wp[o * 16 + j], w1 = Wp[(o + 1) * 16 + j];
            ffma2(a00, x0[j], w0); ffma2(a10, x1[j], w0);
            ffma2(a01, x0[j], w1); ffma2(a11, x1[j], w1);
        }
        float l, h;
        unpack2(a00, l, h); o0p[o] = l + h + bs[o];
        unpack2(a10, l, h); o1p[o] = l + h + bs[o];
        unpack2(a01, l, h); o0p[o + 1] = l + h + bs[o + 1];
        unpack2(a11, l, h); o1p[o + 1] = l + h + bs[o + 1];
    }
}

// ---------------------------------------------------------------------------
extern "C" void kernel_launch(void* const* d_in, const int* in_sizes, int n_in,
                              void* d_out, int out_size) {
    const float* x          = (const float*)d_in[0];  // [1024,1,28,28]
    const float* conv1_w    = (const float*)d_in[1];  // [150,1,9,9]
    const float* chan_emb   = (const float*)d_in[2];  // [150,32]
    const float* in_proj_w  = (const float*)d_in[3];  // [96,32]
    const float* in_proj_b  = (const float*)d_in[4];  // [96]
    const float* out_proj_w = (const float*)d_in[5];  // [32,32]
    const float* out_proj_b = (const float*)d_in[6];  // [32]
    float* out = (float*)d_out;

    prep_w_kernel<<<(81 * NC + 255) / 256, 256>>>(conv1_w);
    pe_kernel<<<NS, ND>>>();
    conv_kernel<<<NB * NH, 160>>>(x);
    select_kernel<<<NB, 512>>>();
    topk_qkv_kernel<<<(NB * NS) / 128, 128>>>(chan_emb, in_proj_w, in_proj_b);
    attn_kernel<<<NB * 2, 224>>>();
    outproj_kernel<<<(NB * NS) / 256, 128>>>(out_proj_w, out_proj_b, out);
}

// round 9
// speedup vs baseline: 2.1961x; 1.0300x over previous
#include <cuda_runtime.h>
#include <math.h>

#define NB 1024
#define NC 150
#define NCP 152     // padded channel stride (float4-aligned); pad stays 0
#define NH 14
#define NS 196      // 14*14
#define ND 32
#define TOTP (NS * NCP)   // padded per-sample extent = 29792
#define KGLB 2352   // ceil(0.08 * 150*196)
#define NHEAD 4
#define HD 8

typedef unsigned long long u64;

__device__ __forceinline__ u64 pack2(float lo, float hi) {
    u64 r; asm("mov.b64 %0, {%1, %2};" : "=l"(r) : "f"(lo), "f"(hi)); return r;
}
__device__ __forceinline__ void unpack2(u64 v, float& lo, float& hi) {
    asm("mov.b64 {%0, %1}, %2;" : "=f"(lo), "=f"(hi) : "l"(v));
}
__device__ __forceinline__ void ffma2(u64& d, u64 a, u64 b) {
    asm("fma.rn.f32x2 %0, %1, %2, %0;" : "+l"(d) : "l"(a), "l"(b));
}
__device__ __forceinline__ u64 fmul2(u64 a, u64 b) {
    u64 r; asm("mul.rn.f32x2 %0, %1, %2;" : "=l"(r) : "l"(a), "l"(b)); return r;
}

__device__ float g_A[(size_t)NB * NS * NCP];       // [b][s][c], c-pad zeroed
__device__ unsigned g_cand[(size_t)NB * TOTP];     // radix-select candidates
__device__ unsigned g_hist[(size_t)NB * 256];      // level-0 hist (from conv)
__device__ unsigned g_maxu[NB];                    // per-sample max (uint view)
__device__ u64 g_wT2[81 * NC];                     // [k][c] = (w,w) splat
__device__ float g_pe[NS * ND];                    // 2D sinusoidal PE table
__device__ float g_thr[NB];
__device__ float g_gmax[NB];
__device__ float g_q[(size_t)NB * NHEAD * NS * HD];
__device__ float g_k[(size_t)NB * NHEAD * NS * HD];
__device__ float g_v[(size_t)NB * NHEAD * NS * HD];
__device__ float g_ctx[(size_t)NB * NS * ND];

// ---------------------------------------------------------------------------
// Kernel 0a: pre-splat conv weights + zero hist/max (graph-replay safe).
// ---------------------------------------------------------------------------
__global__ void prep_w_kernel(const float* __restrict__ w) {
    int i = blockIdx.x * blockDim.x + threadIdx.x;
    if (i < 81 * NC) {
        int k = i / NC, c = i - k * NC;
        float v = w[c * 81 + k];
        g_wT2[i] = pack2(v, v);
    }
    if (i < NB * 256) g_hist[i] = 0u;
    if (i < NB) g_maxu[i] = 0u;
}

// ---------------------------------------------------------------------------
// Kernel 0b: 2D sinusoidal PE table (batch-independent). 196 blocks x 32 thr.
// ---------------------------------------------------------------------------
__global__ void pe_kernel() {
    int s = blockIdx.x;
    int d = threadIdx.x;
    int y = s / NH, xx = s - y * NH;
    const float c0 = -(logf(10000.0f) / 16.0f);
    float pe;
    if (d < 16) {
        int j = d >> 1;
        float div = expf(c0 * (float)(2 * j));
        float ang = (float)y * div;
        pe = (d & 1) ? cosf(ang) : sinf(ang);
    } else {
        int dd = d - 16;
        int j = dd >> 1;
        float div = expf(c0 * (float)(2 * j));
        float ang = (float)xx * div;
        pe = (dd & 1) ? cosf(ang) : sinf(ang);
    }
    g_pe[s * ND + d] = pe;
}

// ---------------------------------------------------------------------------
// Kernel 1: conv 9x9 stride2 pad4 + ReLU, f32x2 over ow-pairs.
// FUSED: builds the per-sample level-0 radix histogram (top byte of each
// nonzero post-ReLU value) and per-sample max while values are in registers.
// ---------------------------------------------------------------------------
__global__ void __launch_bounds__(160) conv_kernel(const float* __restrict__ x) {
    __shared__ float row[9][36];
    __shared__ u64 row2[9][33];
    __shared__ unsigned s_hist[256];
    __shared__ unsigned s_maxu;
    int b = blockIdx.x / NH;
    int oh = blockIdx.x % NH;
    int tid = threadIdx.x;

    for (int i = tid; i < 9 * 36; i += 160)
        (&row[0][0])[i] = 0.0f;
    for (int i = tid; i < 256; i += 160) s_hist[i] = 0u;
    if (tid == 0) s_maxu = 0u;
    __syncthreads();
    for (int i = tid; i < 9 * 28; i += 160) {
        int kh = i / 28, iw = i % 28;
        int ih = oh * 2 - 4 + kh;
        if (ih >= 0 && ih < 28)
            row[kh][iw + 4] = x[((size_t)b * 28 + ih) * 28 + iw];
    }
    __syncthreads();
    for (int i = tid; i < 9 * 33; i += 160) {
        int kh = i / 33, j = i - kh * 33;
        row2[kh][j] = pack2(row[kh][j], row[kh][j + 2]);
    }
    __syncthreads();

    int c = tid;
    if (c < NC) {
        u64 acc[7];
#pragma unroll
        for (int p = 0; p < 7; ++p) acc[p] = 0;
        for (int kh = 0; kh < 9; ++kh) {
            u64 rr2[33];
#pragma unroll
            for (int j = 0; j < 33; ++j) rr2[j] = row2[kh][j];
            const u64* wp = &g_wT2[(kh * 9) * NC + c];
#pragma unroll
            for (int kw = 0; kw < 9; ++kw) {
                u64 w2 = wp[kw * NC];
#pragma unroll
                for (int p = 0; p < 7; ++p)
                    ffma2(acc[p], w2, rr2[4 * p + kw]);
            }
        }
        float* out = &g_A[((size_t)b * NS + oh * NH) * NCP + c];
        unsigned mymax = 0u;
#pragma unroll
        for (int p = 0; p < 7; ++p) {
            float lo, hi; unpack2(acc[p], lo, hi);
            lo = fmaxf(lo, 0.0f);
            hi = fmaxf(hi, 0.0f);
            out[(size_t)(2 * p) * NCP] = lo;
            out[(size_t)(2 * p + 1) * NCP] = hi;
            unsigned ul = __float_as_uint(lo);
            unsigned uh = __float_as_uint(hi);
            mymax = max(mymax, max(ul, uh));
            if (ul) atomicAdd(&s_hist[ul >> 24], 1u);
            if (uh) atomicAdd(&s_hist[uh >> 24], 1u);
        }
        atomicMax(&s_maxu, mymax);
    }
    __syncthreads();
    for (int i = tid; i < 256; i += 160) {
        unsigned cc = s_hist[i];
        if (cc) atomicAdd(&g_hist[(size_t)b * 256 + i], cc);
    }
    if (tid == 0) atomicMax(&g_maxu[b], s_maxu);
}

// ---------------------------------------------------------------------------
// Kernel 2: per-sample exact KGLB-th largest (radix select).
// Level 0 histogram comes precomputed from conv; ONE full pass remains
// (level-1 compaction, 8 values/iter), then two tiny candidate scans.
// Zeros (incl. channel padding) skipped -- safe fall-through semantics.
// ---------------------------------------------------------------------------
__global__ void select_kernel() {
    int b = blockIdx.x;
    const float4* base4 = (const float4*)(g_A + (size_t)b * TOTP);
    unsigned* cand = g_cand + (size_t)b * TOTP;
    __shared__ unsigned hist[256];
    __shared__ unsigned s_prefix;
    __shared__ int s_k;
    __shared__ int s_cnt;
    int tid = threadIdx.x;
    int nt = blockDim.x;
    if (tid == 0) s_cnt = 0;

    // ---- level 0: prefix from precomputed hist ----
    for (int i = tid; i < 256; i += nt) hist[i] = g_hist[(size_t)b * 256 + i];
    __syncthreads();
    if (tid == 0) {
        int cum = 0; unsigned chosen = 0; int kk = KGLB;
        for (int bin = 255; bin >= 0; --bin) {
            int c = (int)hist[bin];
            if (cum + c >= KGLB) { chosen = (unsigned)bin; kk = KGLB - cum; break; }
            cum += c;
        }
        s_prefix = chosen; s_k = kk;
    }
    __syncthreads();
    unsigned prefix = s_prefix;
    int k = s_k;

    // ---- level 1: full pass, compact candidates + hist of 2nd byte ----
    for (int i = tid; i < 256; i += nt) hist[i] = 0;
    __syncthreads();
    for (int i = tid; i < TOTP / 8; i += nt) {
        float4 f0 = base4[2 * i];
        float4 f1 = base4[2 * i + 1];
        unsigned u0 = __float_as_uint(f0.x);
        unsigned u1 = __float_as_uint(f0.y);
        unsigned u2 = __float_as_uint(f0.z);
        unsigned u3 = __float_as_uint(f0.w);
        unsigned u4 = __float_as_uint(f1.x);
        unsigned u5 = __float_as_uint(f1.y);
        unsigned u6 = __float_as_uint(f1.z);
        unsigned u7 = __float_as_uint(f1.w);
        if (u0 && (u0 >> 24) == prefix) { cand[atomicAdd(&s_cnt, 1)] = u0; atomicAdd(&hist[(u0 >> 16) & 255], 1u); }
        if (u1 && (u1 >> 24) == prefix) { cand[atomicAdd(&s_cnt, 1)] = u1; atomicAdd(&hist[(u1 >> 16) & 255], 1u); }
        if (u2 && (u2 >> 24) == prefix) { cand[atomicAdd(&s_cnt, 1)] = u2; atomicAdd(&hist[(u2 >> 16) & 255], 1u); }
        if (u3 && (u3 >> 24) == prefix) { cand[atomicAdd(&s_cnt, 1)] = u3; atomicAdd(&hist[(u3 >> 16) & 255], 1u); }
        if (u4 && (u4 >> 24) == prefix) { cand[atomicAdd(&s_cnt, 1)] = u4; atomicAdd(&hist[(u4 >> 16) & 255], 1u); }
        if (u5 && (u5 >> 24) == prefix) { cand[atomicAdd(&s_cnt, 1)] = u5; atomicAdd(&hist[(u5 >> 16) & 255], 1u); }
        if (u6 && (u6 >> 24) == prefix) { cand[atomicAdd(&s_cnt, 1)] = u6; atomicAdd(&hist[(u6 >> 16) & 255], 1u); }
        if (u7 && (u7 >> 24) == prefix) { cand[atomicAdd(&s_cnt, 1)] = u7; atomicAdd(&hist[(u7 >> 16) & 255], 1u); }
    }
    __syncthreads();
    int cnt = s_cnt;
    if (tid == 0) {
        int cum = 0; unsigned chosen = 0; int kk = k;
        for (int bin = 255; bin >= 0; --bin) {
            int c = (int)hist[bin];
            if (cum + c >= k) { chosen = (unsigned)bin; kk = k - cum; break; }
            cum += c;
        }
        s_prefix = (prefix << 8) | chosen; s_k = kk;
    }
    __syncthreads();
    prefix = s_prefix; k = s_k;

    // ---- level 2: scan candidates ----
    for (int i = tid; i < 256; i += nt) hist[i] = 0;
    __syncthreads();
    for (int i = tid; i < cnt; i += nt) {
        unsigned u = cand[i];
        if ((u >> 16) == prefix) atomicAdd(&hist[(u >> 8) & 255], 1u);
    }
    __syncthreads();
    if (tid == 0) {
        int cum = 0; unsigned chosen = 0; int kk = k;
        for (int bin = 255; bin >= 0; --bin) {
            int c = (int)hist[bin];
            if (cum + c >= k) { chosen = (unsigned)bin; kk = k - cum; break; }
            cum += c;
        }
        s_prefix = (prefix << 8) | chosen; s_k = kk;
    }
    __syncthreads();
    prefix = s_prefix; k = s_k;

    // ---- level 3: scan candidates ----
    for (int i = tid; i < 256; i += nt) hist[i] = 0;
    __syncthreads();
    for (int i = tid; i < cnt; i += nt) {
        unsigned u = cand[i];
        if ((u >> 8) == prefix) atomicAdd(&hist[u & 255], 1u);
    }
    __syncthreads();
    if (tid == 0) {
        int cum = 0; unsigned chosen = 0;
        for (int bin = 255; bin >= 0; --bin) {
            int c = (int)hist[bin];
            if (cum + c >= k) { chosen = (unsigned)bin; break; }
            cum += c;
        }
        g_thr[b] = __uint_as_float((prefix << 8) | chosen);
        g_gmax[b] = __uint_as_float(g_maxu[b]);
    }
}

// ---------------------------------------------------------------------------
// Kernel 3 (FUSED): per-location top-10 + scatter embed + /gmax + PE + qkv.
// One THREAD per location; padded row stride (152) keeps float4 loads aligned.
// ---------------------------------------------------------------------------
__global__ void __launch_bounds__(128) topk_qkv_kernel(
        const float* __restrict__ chan_emb,     // [150][32]
        const float* __restrict__ W,            // [96][32]
        const float* __restrict__ bias) {       // [96]
    __shared__ u64 Emb[NC * 16];   // 19.2 KB
    __shared__ u64 Wp[96 * 16];    // 12.3 KB
    __shared__ float bs[96];
    int tid = threadIdx.x;
    {
        const float2* e2 = (const float2*)chan_emb;
        for (int i = tid; i < NC * 16; i += 128) {
            float2 f = e2[i]; Emb[i] = pack2(f.x, f.y);
        }
        const float2* w2 = (const float2*)W;
        for (int i = tid; i < 96 * 16; i += 128) {
            float2 f = w2[i]; Wp[i] = pack2(f.x, f.y);
        }
        if (tid < 96) bs[tid] = bias[tid];
    }
    __syncthreads();

    int loc = blockIdx.x * 128 + tid;          // exact: grid = NB*NS/128
    int b = loc / NS, s = loc - b * NS;
    float th = g_thr[b];
    float gm = g_gmax[b];
    float inv = (gm > 0.0f) ? (1.0f / gm) : 0.0f;

    // ---- top-10 scan (ascending channel order; 38 aligned float4) ----
    float tv[10];
    int tc[10];
#pragma unroll
    for (int j = 0; j < 10; ++j) { tv[j] = 0.0f; tc[j] = 0; }

    const float4* r4 = (const float4*)(g_A + (size_t)loc * NCP);
#pragma unroll 4
    for (int i = 0; i < 38; ++i) {
        float4 f = r4[i];
        float vals[4] = {f.x, f.y, f.z, f.w};
#pragma unroll
        for (int q = 0; q < 4; ++q) {
            float a = vals[q];
            if (a >= th && a > tv[9]) {
                float cv = a; int cc = 4 * i + q;
#pragma unroll
                for (int j = 0; j < 10; ++j) {
                    bool sw = cv > tv[j];
                    float nv = sw ? tv[j] : cv;
                    int nc2 = sw ? tc[j] : cc;
                    tv[j] = sw ? cv : tv[j];
                    tc[j] = sw ? cc : tc[j];
                    cv = nv; cc = nc2;
                }
            }
        }
    }

    // ---- embed accumulate ----
    u64 x[16];
#pragma unroll
    for (int t = 0; t < 16; ++t) x[t] = 0;
#pragma unroll
    for (int j = 0; j < 10; ++j) {
        if (tv[j] > 0.0f) {
            u64 vv = pack2(tv[j], tv[j]);
            const u64* ep = &Emb[tc[j] * 16];
#pragma unroll
            for (int t = 0; t < 16; ++t)
                ffma2(x[t], vv, ep[t]);
        }
    }

    // ---- normalize + PE ----
    {
        u64 inv2 = pack2(inv, inv);
        const float4* pe4 = (const float4*)(g_pe + s * ND);
#pragma unroll
        for (int t = 0; t < 8; ++t) {
            float4 p = pe4[t];
            u64 y0 = pack2(p.x, p.y);
            u64 y1 = pack2(p.z, p.w);
            ffma2(y0, x[2 * t], inv2);
            ffma2(y1, x[2 * t + 1], inv2);
            x[2 * t] = y0;
            x[2 * t + 1] = y1;
        }
    }

    // ---- qkv projection: 96 outputs, 4 at a time ----
    size_t qb = (size_t)b * (NHEAD * NS * HD) + (size_t)s * HD;
    const float SC = 0.3535533905932738f;  // 1/sqrt(8)

#pragma unroll 2
    for (int o = 0; o < 32; o += 4) {
        u64 a0 = 0, a1 = 0, a2 = 0, a3 = 0;
#pragma unroll
        for (int j = 0; j < 16; ++j) {
            u64 xv = x[j];
            ffma2(a0, xv, Wp[(o + 0) * 16 + j]);
            ffma2(a1, xv, Wp[(o + 1) * 16 + j]);
            ffma2(a2, xv, Wp[(o + 2) * 16 + j]);
            ffma2(a3, xv, Wp[(o + 3) * 16 + j]);
        }
        float l, h, r0, r1, r2, r3;
        unpack2(a0, l, h); r0 = (l + h + bs[o + 0]) * SC;
        unpack2(a1, l, h); r1 = (l + h + bs[o + 1]) * SC;
        unpack2(a2, l, h); r2 = (l + h + bs[o + 2]) * SC;
        unpack2(a3, l, h); r3 = (l + h + bs[o + 3]) * SC;
        *(float4*)(g_q + qb + (o >> 3) * (NS * HD) + (o & 7)) = make_float4(r0, r1, r2, r3);
    }
#pragma unroll 2
    for (int o = 32; o < 64; o += 4) {
        u64 a0 = 0, a1 = 0, a2 = 0, a3 = 0;
#pragma unroll
        for (int j = 0; j < 16; ++j) {
            u64 xv = x[j];
            ffma2(a0, xv, Wp[(o + 0) * 16 + j]);
            ffma2(a1, xv, Wp[(o + 1) * 16 + j]);
            ffma2(a2, xv, Wp[(o + 2) * 16 + j]);
            ffma2(a3, xv, Wp[(o + 3) * 16 + j]);
        }
        float l, h, r0, r1, r2, r3;
        unpack2(a0, l, h); r0 = l + h + bs[o + 0];
        unpack2(a1, l, h); r1 = l + h + bs[o + 1];
        unpack2(a2, l, h); r2 = l + h + bs[o + 2];
        unpack2(a3, l, h); r3 = l + h + bs[o + 3];
        int d = o - 32;
        *(float4*)(g_k + qb + (d >> 3) * (NS * HD) + (d & 7)) = make_float4(r0, r1, r2, r3);
    }
#pragma unroll 2
    for (int o = 64; o < 96; o += 4) {
        u64 a0 = 0, a1 = 0, a2 = 0, a3 = 0;
#pragma unroll
        for (int j = 0; j < 16; ++j) {
            u64 xv = x[j];
            ffma2(a0, xv, Wp[(o + 0) * 16 + j]);
            ffma2(a1, xv, Wp[(o + 1) * 16 + j]);
            ffma2(a2, xv, Wp[(o + 2) * 16 + j]);
            ffma2(a3, xv, Wp[(o + 3) * 16 + j]);
        }
        float l, h, r0, r1, r2, r3;
        unpack2(a0, l, h); r0 = l + h + bs[o + 0];
        unpack2(a1, l, h); r1 = l + h + bs[o + 1];
        unpack2(a2, l, h); r2 = l + h + bs[o + 2];
        unpack2(a3, l, h); r3 = l + h + bs[o + 3];
        int d = o - 64;
        *(float4*)(g_v + qb + (d >> 3) * (NS * HD) + (d & 7)) = make_float4(r0, r1, r2, r3);
    }
}

// ---------------------------------------------------------------------------
// Kernel 4b: attention. Block = (b, head-pair): 2 heads, 224 threads.
// Single-pass EXACT softmax via Cauchy-Schwarz bound m' = |q| * max|k|.
// ---------------------------------------------------------------------------
__global__ void __launch_bounds__(224) attn_kernel() {
    __shared__ __align__(16) u64 K2[2 * NS * 4];
    __shared__ __align__(16) u64 V2[2 * NS * 4];
    __shared__ unsigned s_kmax[2];
    int b = blockIdx.x >> 1;
    int hp = blockIdx.x & 1;
    int tid = threadIdx.x;
    if (tid < 2) s_kmax[tid] = 0u;

    const float4* kp4 = (const float4*)(g_k + (((size_t)b * NHEAD + hp * 2) * NS) * HD);
    const float4* vp4 = (const float4*)(g_v + (((size_t)b * NHEAD + hp * 2) * NS) * HD);
    for (int i = tid; i < 2 * NS * 2; i += 224) {
        float4 f = kp4[i];
        K2[i * 2] = pack2(f.x, f.y);
        K2[i * 2 + 1] = pack2(f.z, f.w);
        float4 g = vp4[i];
        V2[i * 2] = pack2(g.x, g.y);
        V2[i * 2 + 1] = pack2(g.z, g.w);
    }
    __syncthreads();

    for (int r = tid; r < 2 * NS; r += 224) {
        u64 n2 = fmul2(K2[r * 4], K2[r * 4]);
        ffma2(n2, K2[r * 4 + 1], K2[r * 4 + 1]);
        ffma2(n2, K2[r * 4 + 2], K2[r * 4 + 2]);
        ffma2(n2, K2[r * 4 + 3], K2[r * 4 + 3]);
        float lo, hi; unpack2(n2, lo, hi);
        atomicMax(&s_kmax[r >= NS ? 1 : 0], __float_as_uint(lo + hi));
    }
    __syncthreads();

    int ha = tid / 112;
    int i = tid - ha * 112;
    if (i < 98) {
        int head = hp * 2 + ha;
        int q0 = 2 * i, q1 = 2 * i + 1;
        size_t qrow = (((size_t)b * NHEAD + head) * NS);
        const float4* qp0 = (const float4*)(g_q + (qrow + q0) * HD);
        const float4* qp1 = (const float4*)(g_q + (qrow + q1) * HD);
        float4 qa = qp0[0], qb = qp0[1], qc = qp1[0], qd = qp1[1];
        u64 Q0[4], Q1[4];
        Q0[0] = pack2(qa.x, qa.y); Q0[1] = pack2(qa.z, qa.w);
        Q0[2] = pack2(qb.x, qb.y); Q0[3] = pack2(qb.z, qb.w);
        Q1[0] = pack2(qc.x, qc.y); Q1[1] = pack2(qc.z, qc.w);
        Q1[2] = pack2(qd.x, qd.y); Q1[3] = pack2(qd.z, qd.w);

        float km = __uint_as_float(s_kmax[ha]);
        u64 n0 = fmul2(Q0[0], Q0[0]);
        ffma2(n0, Q0[1], Q0[1]); ffma2(n0, Q0[2], Q0[2]); ffma2(n0, Q0[3], Q0[3]);
        u64 n1 = fmul2(Q1[0], Q1[0]);
        ffma2(n1, Q1[1], Q1[1]); ffma2(n1, Q1[2], Q1[2]); ffma2(n1, Q1[3], Q1[3]);
        float a0, a1, b0f, b1f;
        unpack2(n0, a0, a1); unpack2(n1, b0f, b1f);
        float m0 = sqrtf((a0 + a1) * km);
        float m1 = sqrtf((b0f + b1f) * km);

        float l0 = 0.0f, l1 = 0.0f;
        u64 A0 = 0, A1 = 0, A2 = 0, A3 = 0;
        u64 B0 = 0, B1 = 0, B2 = 0, B3 = 0;
        const ulonglong2* KK = (const ulonglong2*)(K2 + ha * NS * 4);
        const ulonglong2* VV = (const ulonglong2*)(V2 + ha * NS * 4);
#pragma unroll 2
        for (int t = 0; t < NS; ++t) {
            ulonglong2 ka = KK[t * 2], kb = KK[t * 2 + 1];
            u64 d0 = fmul2(Q0[0], ka.x);
            ffma2(d0, Q0[1], ka.y); ffma2(d0, Q0[2], kb.x); ffma2(d0, Q0[3], kb.y);
            u64 d1 = fmul2(Q1[0], ka.x);
            ffma2(d1, Q1[1], ka.y); ffma2(d1, Q1[2], kb.x); ffma2(d1, Q1[3], kb.y);
            float e0, f0, e1, f1;
            unpack2(d0, e0, f0); unpack2(d1, e1, f1);
            float p0 = __expf(e0 + f0 - m0);
            float p1 = __expf(e1 + f1 - m1);
            l0 += p0; l1 += p1;
            u64 p02 = pack2(p0, p0), p12 = pack2(p1, p1);
            ulonglong2 va = VV[t * 2], vb = VV[t * 2 + 1];
            ffma2(A0, p02, va.x); ffma2(A1, p02, va.y);
            ffma2(A2, p02, vb.x); ffma2(A3, p02, vb.y);
            ffma2(B0, p12, va.x); ffma2(B1, p12, va.y);
            ffma2(B2, p12, vb.x); ffma2(B3, p12, vb.y);
        }
        float inv0 = 1.0f / l0, inv1 = 1.0f / l1;
        float o0, o1, o2, o3, o4, o5, o6, o7;
        unpack2(A0, o0, o1); unpack2(A1, o2, o3);
        unpack2(A2, o4, o5); unpack2(A3, o6, o7);
        float4* cp0 = (float4*)(g_ctx + ((size_t)b * NS + q0) * ND + head * HD);
        cp0[0] = make_float4(o0 * inv0, o1 * inv0, o2 * inv0, o3 * inv0);
        cp0[1] = make_float4(o4 * inv0, o5 * inv0, o6 * inv0, o7 * inv0);
        unpack2(B0, o0, o1); unpack2(B1, o2, o3);
        unpack2(B2, o4, o5); unpack2(B3, o6, o7);
        float4* cp1 = (float4*)(g_ctx + ((size_t)b * NS + q1) * ND + head * HD);
        cp1[0] = make_float4(o0 * inv1, o1 * inv1, o2 * inv1, o3 * inv1);
        cp1[1] = make_float4(o4 * inv1, o5 * inv1, o6 * inv1, o7 * inv1);
    }
}

// ---------------------------------------------------------------------------
// Kernel 5: out projection, f32x2 register-tiled, o-pairs. 128 thr, 2 rows.
// ---------------------------------------------------------------------------
__global__ void __launch_bounds__(128) outproj_kernel(const float* __restrict__ W,
                                                      const float* __restrict__ bias,
                                                      float* __restrict__ out) {
    __shared__ u64 Wp[32 * 16];
    __shared__ float bs[32];
    int tid = threadIdx.x;
    {
        const float2* w2 = (const float2*)W;
        for (int i = tid; i < 32 * 16; i += 128) {
            float2 f = w2[i];
            Wp[i] = pack2(f.x, f.y);
        }
        if (tid < 32) bs[tid] = bias[tid];
    }
    __syncthreads();

    int r0 = blockIdx.x * 256 + tid;
    int r1 = r0 + 128;

    u64 x0[16], x1[16];
    {
        const float4* p0 = (const float4*)(g_ctx + (size_t)r0 * ND);
        const float4* p1 = (const float4*)(g_ctx + (size_t)r1 * ND);
#pragma unroll
        for (int i = 0; i < 8; ++i) {
            float4 f = p0[i];
            x0[2 * i] = pack2(f.x, f.y); x0[2 * i + 1] = pack2(f.z, f.w);
            float4 g = p1[i];
            x1[2 * i] = pack2(g.x, g.y); x1[2 * i + 1] = pack2(g.z, g.w);
        }
    }

    float* o0p = out + (size_t)r0 * ND;
    float* o1p = out + (size_t)r1 * ND;
#pragma unroll 2
    for (int o = 0; o < 32; o += 2) {
        u64 a00 = 0, a10 = 0, a01 = 0, a11 = 0;
#pragma unroll
        for (int j = 0; j < 16; ++j) {
            u64 w0 = Wp[o * 16 + j], w1 = Wp[(o + 1) * 16 + j];
            ffma2(a00, x0[j], w0); ffma2(a10, x1[j], w0);
            ffma2(a01, x0[j], w1); ffma2(a11, x1[j], w1);
        }
        float l, h;
        unpack2(a00, l, h); o0p[o] = l + h + bs[o];
        unpack2(a10, l, h); o1p[o] = l + h + bs[o];
        unpack2(a01, l, h); o0p[o + 1] = l + h + bs[o + 1];
        unpack2(a11, l, h); o1p[o + 1] = l + h + bs[o + 1];
    }
}

// ---------------------------------------------------------------------------
extern "C" void kernel_launch(void* const* d_in, const int* in_sizes, int n_in,
                              void* d_out, int out_size) {
    const float* x          = (const float*)d_in[0];  // [1024,1,28,28]
    const float* conv1_w    = (const float*)d_in[1];  // [150,1,9,9]
    const float* chan_emb   = (const float*)d_in[2];  // [150,32]
    const float* in_proj_w  = (const float*)d_in[3];  // [96,32]
    const float* in_proj_b  = (const float*)d_in[4];  // [96]
    const float* out_proj_w = (const float*)d_in[5];  // [32,32]
    const float* out_proj_b = (const float*)d_in[6];  // [32]
    float* out = (float*)d_out;

    prep_w_kernel<<<(NB * 256 + 255) / 256, 256>>>(conv1_w);
    pe_kernel<<<NS, ND>>>();
    conv_kernel<<<NB * NH, 160>>>(x);
    select_kernel<<<NB, 512>>>();
    topk_qkv_kernel<<<(NB * NS) / 128, 128>>>(chan_emb, in_proj_w, in_proj_b);
    attn_kernel<<<NB * 2, 224>>>();
    outproj_kernel<<<(NB * NS) / 256, 128>>>(out_proj_w, out_proj_b, out);
}